// round 2
// baseline (speedup 1.0000x reference)
#include <cuda_runtime.h>

#define NMAX 100000
#define IND 128
#define HID 128
#define OUTD 64

// Scratch (static __device__ — allocation-free per harness rules)
__device__ int   g_degc[NMAX];
__device__ float g_dinv[NMAX];
__device__ float g_aggx[(size_t)NMAX * IND];   // aggregated x (layer-1 pre-GEMM)
__device__ float g_h[(size_t)NMAX * HID];      // relu(aggx@W1+b1)
__device__ float g_h2[(size_t)NMAX * OUTD];    // h@W2 (pre-aggregation)

__global__ void zero_deg_k(int n) {
    int i = blockIdx.x * blockDim.x + threadIdx.x;
    if (i < n) g_degc[i] = 0;
}

__global__ void deg_k(const int* __restrict__ dst, int E) {
    int i = blockIdx.x * blockDim.x + threadIdx.x;
    if (i < E) atomicAdd(&g_degc[dst[i]], 1);
}

__global__ void dinv_k(int n) {
    int i = blockIdx.x * blockDim.x + threadIdx.x;
    if (i < n) g_dinv[i] = rsqrtf((float)g_degc[i] + 1.0f);
}

// aggx[i] = x[i] * dinv[i]^2   (self-loop contribution, also inits aggx)
__global__ void init1_k(const float* __restrict__ x, int n) {
    int i = blockIdx.x * blockDim.x + threadIdx.x; // over n * (IND/4) float4 chunks
    int total = n * (IND / 4);
    if (i < total) {
        int r = i / (IND / 4);
        float dv = g_dinv[r];
        float d2 = dv * dv;
        float4 v = ((const float4*)x)[i];
        v.x *= d2; v.y *= d2; v.z *= d2; v.w *= d2;
        ((float4*)g_aggx)[i] = v;
    }
}

// Layer-1 edge aggregation: aggx[dst] += x[src] * dinv[src]*dinv[dst]  (128-d)
// One warp handles one edge: 32 lanes x float4 = 128 floats.
__global__ void edge_agg1_k(const float* __restrict__ x,
                            const int* __restrict__ src,
                            const int* __restrict__ dst, int E) {
    int gtid = blockIdx.x * blockDim.x + threadIdx.x;
    int e = gtid >> 5;          // warp id = edge id
    int c = gtid & 31;          // lane = float4 chunk
    if (e >= E) return;
    int s = src[e], d = dst[e];
    float nm = g_dinv[s] * g_dinv[d];
    float4 v = ((const float4*)(x + (size_t)s * IND))[c];
    float* p = g_aggx + (size_t)d * IND + (size_t)c * 4;
    asm volatile("red.global.add.v4.f32 [%0], {%1,%2,%3,%4};"
                 :: "l"(p), "f"(v.x * nm), "f"(v.y * nm), "f"(v.z * nm), "f"(v.w * nm)
                 : "memory");
}

// Layer-2 edge aggregation: out[dst] += h2[src] * dinv[src]*dinv[dst]  (64-d)
// Half-warp (16 lanes) per edge.
__global__ void edge_agg2_k(const int* __restrict__ src,
                            const int* __restrict__ dst,
                            float* __restrict__ out, int E) {
    int gtid = blockIdx.x * blockDim.x + threadIdx.x;
    int e = gtid >> 4;
    int c = gtid & 15;
    if (e >= E) return;
    int s = src[e], d = dst[e];
    float nm = g_dinv[s] * g_dinv[d];
    float4 v = ((const float4*)(g_h2 + (size_t)s * OUTD))[c];
    float* p = out + (size_t)d * OUTD + (size_t)c * 4;
    asm volatile("red.global.add.v4.f32 [%0], {%1,%2,%3,%4};"
                 :: "l"(p), "f"(v.x * nm), "f"(v.y * nm), "f"(v.z * nm), "f"(v.w * nm)
                 : "memory");
}

// GEMM1: g_h = relu(g_aggx @ W1 + b1)     [n x 128] @ [128 x 128]
// Tile: 32 rows x 128 cols per block, 256 threads, 4x4 micro-tile.
__global__ void gemm1_k(const float* __restrict__ W, const float* __restrict__ b, int n) {
    extern __shared__ float sm[];
    float* ws = sm;            // 128*128 = 16384 floats
    float* xs = sm + 16384;    // 32*128  = 4096 floats
    int tid = threadIdx.x;
    for (int i = tid; i < 4096; i += 256)
        ((float4*)ws)[i] = ((const float4*)W)[i];
    int row0 = blockIdx.x * 32;
    for (int i = tid; i < 1024; i += 256) {
        int r = i >> 5, c = i & 31;
        int gr = row0 + r;
        float4 v = (gr < n) ? ((const float4*)(g_aggx + (size_t)gr * 128))[c]
                            : make_float4(0.f, 0.f, 0.f, 0.f);
        ((float4*)xs)[i] = v;
    }
    __syncthreads();
    int tx = tid & 31, ty = tid >> 5;
    float acc[4][4] = {};
    const float* x0 = xs + ty * 4 * 128;
#pragma unroll 4
    for (int k = 0; k < 128; k++) {
        float4 bv = ((const float4*)(ws + k * 128))[tx];
        float a0 = x0[k], a1 = x0[128 + k], a2 = x0[256 + k], a3 = x0[384 + k];
        acc[0][0] += a0 * bv.x; acc[0][1] += a0 * bv.y; acc[0][2] += a0 * bv.z; acc[0][3] += a0 * bv.w;
        acc[1][0] += a1 * bv.x; acc[1][1] += a1 * bv.y; acc[1][2] += a1 * bv.z; acc[1][3] += a1 * bv.w;
        acc[2][0] += a2 * bv.x; acc[2][1] += a2 * bv.y; acc[2][2] += a2 * bv.z; acc[2][3] += a2 * bv.w;
        acc[3][0] += a3 * bv.x; acc[3][1] += a3 * bv.y; acc[3][2] += a3 * bv.z; acc[3][3] += a3 * bv.w;
    }
    float4 bb = ((const float4*)b)[tx];
#pragma unroll
    for (int i = 0; i < 4; i++) {
        int gr = row0 + ty * 4 + i;
        if (gr < n) {
            float4 o;
            o.x = fmaxf(acc[i][0] + bb.x, 0.f);
            o.y = fmaxf(acc[i][1] + bb.y, 0.f);
            o.z = fmaxf(acc[i][2] + bb.z, 0.f);
            o.w = fmaxf(acc[i][3] + bb.w, 0.f);
            ((float4*)(g_h + (size_t)gr * 128))[tx] = o;
        }
    }
}

// GEMM2 fused: g_h2 = g_h @ W2;  out = g_h2 * dinv^2 + b2  (init for scatter)
// Tile: 64 rows x 64 cols per block, 256 threads, 4x4 micro-tile.
__global__ void gemm2_k(const float* __restrict__ W, const float* __restrict__ b,
                        float* __restrict__ out, int n) {
    extern __shared__ float sm[];
    float* ws = sm;           // 128*64 = 8192 floats
    float* xs = sm + 8192;    // 64*128 = 8192 floats
    int tid = threadIdx.x;
    for (int i = tid; i < 2048; i += 256)
        ((float4*)ws)[i] = ((const float4*)W)[i];
    int row0 = blockIdx.x * 64;
    for (int i = tid; i < 2048; i += 256) {
        int r = i >> 5, c = i & 31;
        int gr = row0 + r;
        float4 v = (gr < n) ? ((const float4*)(g_h + (size_t)gr * 128))[c]
                            : make_float4(0.f, 0.f, 0.f, 0.f);
        ((float4*)xs)[i] = v;
    }
    __syncthreads();
    int tx = tid & 15, ty = tid >> 4;
    float acc[4][4] = {};
    const float* x0 = xs + ty * 4 * 128;
#pragma unroll 4
    for (int k = 0; k < 128; k++) {
        float4 bv = ((const float4*)(ws + k * 64))[tx];
        float a0 = x0[k], a1 = x0[128 + k], a2 = x0[256 + k], a3 = x0[384 + k];
        acc[0][0] += a0 * bv.x; acc[0][1] += a0 * bv.y; acc[0][2] += a0 * bv.z; acc[0][3] += a0 * bv.w;
        acc[1][0] += a1 * bv.x; acc[1][1] += a1 * bv.y; acc[1][2] += a1 * bv.z; acc[1][3] += a1 * bv.w;
        acc[2][0] += a2 * bv.x; acc[2][1] += a2 * bv.y; acc[2][2] += a2 * bv.z; acc[2][3] += a2 * bv.w;
        acc[3][0] += a3 * bv.x; acc[3][1] += a3 * bv.y; acc[3][2] += a3 * bv.z; acc[3][3] += a3 * bv.w;
    }
    float4 bb = ((const float4*)b)[tx];
#pragma unroll
    for (int i = 0; i < 4; i++) {
        int gr = row0 + ty * 4 + i;
        if (gr < n) {
            float dv = g_dinv[gr];
            float d2 = dv * dv;
            float4 h2v = make_float4(acc[i][0], acc[i][1], acc[i][2], acc[i][3]);
            ((float4*)(g_h2 + (size_t)gr * 64))[tx] = h2v;
            float4 o;
            o.x = h2v.x * d2 + bb.x;
            o.y = h2v.y * d2 + bb.y;
            o.z = h2v.z * d2 + bb.z;
            o.w = h2v.w * d2 + bb.w;
            ((float4*)(out + (size_t)gr * 64))[tx] = o;
        }
    }
}

extern "C" void kernel_launch(void* const* d_in, const int* in_sizes, int n_in,
                              void* d_out, int out_size) {
    const float* x   = (const float*)d_in[0];
    const int*   ei  = (const int*)d_in[1];   // int32: JAX x64 disabled
    const float* W1  = (const float*)d_in[2];
    const float* b1  = (const float*)d_in[3];
    const float* W2  = (const float*)d_in[4];
    const float* b2  = (const float*)d_in[5];
    float* out       = (float*)d_out;

    int n = in_sizes[0] / IND;
    int E = in_sizes[1] / 2;
    const int* src = ei;
    const int* dst = ei + E;

    cudaFuncSetAttribute(gemm1_k, cudaFuncAttributeMaxDynamicSharedMemorySize, 20480 * 4);
    cudaFuncSetAttribute(gemm2_k, cudaFuncAttributeMaxDynamicSharedMemorySize, 16384 * 4);

    const int TB = 256;
    // degrees -> dinv
    zero_deg_k<<<(n + TB - 1) / TB, TB>>>(n);
    deg_k<<<(E + TB - 1) / TB, TB>>>(dst, E);
    dinv_k<<<(n + TB - 1) / TB, TB>>>(n);
    // layer 1: aggregate x, then GEMM+bias+relu
    init1_k<<<(n * (IND / 4) + TB - 1) / TB, TB>>>(x, n);
    long long t1 = (long long)E * 32;
    edge_agg1_k<<<(int)((t1 + TB - 1) / TB), TB>>>(x, src, dst, E);
    gemm1_k<<<(n + 31) / 32, TB, 20480 * 4>>>(W1, b1, n);
    // layer 2: GEMM first (fused out-init), then aggregate 64-d
    gemm2_k<<<(n + 63) / 64, TB, 16384 * 4>>>(W2, b2, out, n);
    long long t2 = (long long)E * 16;
    edge_agg2_k<<<(int)((t2 + TB - 1) / TB), TB>>>(src, dst, out, E);
}

// round 3
// speedup vs baseline: 1.0805x; 1.0805x over previous
#include <cuda_runtime.h>

#define NMAX 100000
#define EMAX 1600000
#define IND 128
#define HID 128
#define OUTD 64

// Scratch (static __device__ — allocation-free per harness rules)
__device__ int   g_degc[NMAX];
__device__ float g_dinv[NMAX];
__device__ int   g_rowptr[NMAX + 1];
__device__ int   g_pos[NMAX];
__device__ int   g_csr_src[EMAX];
__device__ float g_aggx[(size_t)NMAX * IND];   // aggregated x (layer-1 pre-GEMM)
__device__ float g_h[(size_t)NMAX * HID];      // relu(aggx@W1+b1)
__device__ float g_h2[(size_t)NMAX * OUTD];    // h@W2 (pre-aggregation)

__global__ void zero_deg_k(int n) {
    int i = blockIdx.x * blockDim.x + threadIdx.x;
    if (i < n) g_degc[i] = 0;
}

__global__ void deg_k(const int* __restrict__ dst, int E) {
    int i = blockIdx.x * blockDim.x + threadIdx.x;
    if (i < E) atomicAdd(&g_degc[dst[i]], 1);
}

__global__ void dinv_k(int n) {
    int i = blockIdx.x * blockDim.x + threadIdx.x;
    if (i < n) g_dinv[i] = rsqrtf((float)g_degc[i] + 1.0f);
}

// Single-block exclusive scan of degrees -> rowptr, and init pos=rowptr.
__global__ void scan_k(int n) {
    __shared__ int part[1024];
    int t = threadIdx.x;
    int chunk = (n + 1023) / 1024;
    int lo = t * chunk;
    int hi = min(n, lo + chunk);
    int s = 0;
    for (int i = lo; i < hi; i++) s += g_degc[i];
    part[t] = s;
    __syncthreads();
    // Hillis-Steele inclusive scan
    for (int off = 1; off < 1024; off <<= 1) {
        int v = (t >= off) ? part[t - off] : 0;
        __syncthreads();
        part[t] += v;
        __syncthreads();
    }
    int run = (t == 0) ? 0 : part[t - 1];
    for (int i = lo; i < hi; i++) {
        g_rowptr[i] = run;
        g_pos[i] = run;
        run += g_degc[i];
    }
    if (hi == n) g_rowptr[n] = run;
}

// Scatter src ids into dst-sorted CSR slots.
__global__ void scatter_k(const int* __restrict__ src,
                          const int* __restrict__ dst, int E) {
    int e = blockIdx.x * blockDim.x + threadIdx.x;
    if (e < E) {
        int d = dst[e];
        int p = atomicAdd(&g_pos[d], 1);
        g_csr_src[p] = src[e];
    }
}

// Layer-1 aggregation (CSR, warp per dst node, 128-d):
// aggx[i] = x[i]*dinv[i]^2 + sum_j x[src_j] * dinv[src_j]*dinv[i]
__global__ void agg1_k(const float* __restrict__ x, int n) {
    int w = (blockIdx.x * blockDim.x + threadIdx.x) >> 5;
    if (w >= n) return;
    int c = threadIdx.x & 31;
    float di = g_dinv[w];
    float d2 = di * di;
    float4 acc = ((const float4*)(x + (size_t)w * IND))[c];
    acc.x *= d2; acc.y *= d2; acc.z *= d2; acc.w *= d2;
    int j = g_rowptr[w], end = g_rowptr[w + 1];
    for (; j + 1 < end; j += 2) {
        int s0 = __ldg(&g_csr_src[j]);
        int s1 = __ldg(&g_csr_src[j + 1]);
        float nm0 = __ldg(&g_dinv[s0]) * di;
        float nm1 = __ldg(&g_dinv[s1]) * di;
        float4 v0 = __ldg((const float4*)(x + (size_t)s0 * IND) + c);
        float4 v1 = __ldg((const float4*)(x + (size_t)s1 * IND) + c);
        acc.x += v0.x * nm0; acc.y += v0.y * nm0; acc.z += v0.z * nm0; acc.w += v0.w * nm0;
        acc.x += v1.x * nm1; acc.y += v1.y * nm1; acc.z += v1.z * nm1; acc.w += v1.w * nm1;
    }
    if (j < end) {
        int s = __ldg(&g_csr_src[j]);
        float nm = __ldg(&g_dinv[s]) * di;
        float4 v = __ldg((const float4*)(x + (size_t)s * IND) + c);
        acc.x += v.x * nm; acc.y += v.y * nm; acc.z += v.z * nm; acc.w += v.w * nm;
    }
    ((float4*)(g_aggx + (size_t)w * IND))[c] = acc;
}

// Layer-2 aggregation (CSR, warp per dst node, 64-d, float2 per lane):
// out[i] = h2[i]*dinv[i]^2 + b2 + sum_j h2[src_j]*dinv[src_j]*dinv[i]
__global__ void agg2_k(const float* __restrict__ b2,
                       float* __restrict__ out, int n) {
    int w = (blockIdx.x * blockDim.x + threadIdx.x) >> 5;
    if (w >= n) return;
    int c = threadIdx.x & 31;
    float di = g_dinv[w];
    float d2 = di * di;
    float2 bb = ((const float2*)b2)[c];
    float2 self = ((const float2*)(g_h2 + (size_t)w * OUTD))[c];
    float2 acc;
    acc.x = self.x * d2 + bb.x;
    acc.y = self.y * d2 + bb.y;
    int j = g_rowptr[w], end = g_rowptr[w + 1];
    for (; j + 1 < end; j += 2) {
        int s0 = __ldg(&g_csr_src[j]);
        int s1 = __ldg(&g_csr_src[j + 1]);
        float nm0 = __ldg(&g_dinv[s0]) * di;
        float nm1 = __ldg(&g_dinv[s1]) * di;
        float2 v0 = __ldg((const float2*)(g_h2 + (size_t)s0 * OUTD) + c);
        float2 v1 = __ldg((const float2*)(g_h2 + (size_t)s1 * OUTD) + c);
        acc.x += v0.x * nm0; acc.y += v0.y * nm0;
        acc.x += v1.x * nm1; acc.y += v1.y * nm1;
    }
    if (j < end) {
        int s = __ldg(&g_csr_src[j]);
        float nm = __ldg(&g_dinv[s]) * di;
        float2 v = __ldg((const float2*)(g_h2 + (size_t)s * OUTD) + c);
        acc.x += v.x * nm; acc.y += v.y * nm;
    }
    ((float2*)(out + (size_t)w * OUTD))[c] = acc;
}

// GEMM1: g_h = relu(g_aggx @ W1 + b1)     [n x 128] @ [128 x 128]
__global__ void gemm1_k(const float* __restrict__ W, const float* __restrict__ b, int n) {
    extern __shared__ float sm[];
    float* ws = sm;            // 128*128 = 16384 floats
    float* xs = sm + 16384;    // 32*128  = 4096 floats
    int tid = threadIdx.x;
    for (int i = tid; i < 4096; i += 256)
        ((float4*)ws)[i] = ((const float4*)W)[i];
    int row0 = blockIdx.x * 32;
    for (int i = tid; i < 1024; i += 256) {
        int r = i >> 5, c = i & 31;
        int gr = row0 + r;
        float4 v = (gr < n) ? ((const float4*)(g_aggx + (size_t)gr * 128))[c]
                            : make_float4(0.f, 0.f, 0.f, 0.f);
        ((float4*)xs)[i] = v;
    }
    __syncthreads();
    int tx = tid & 31, ty = tid >> 5;
    float acc[4][4] = {};
    const float* x0 = xs + ty * 4 * 128;
#pragma unroll 4
    for (int k = 0; k < 128; k++) {
        float4 bv = ((const float4*)(ws + k * 128))[tx];
        float a0 = x0[k], a1 = x0[128 + k], a2 = x0[256 + k], a3 = x0[384 + k];
        acc[0][0] += a0 * bv.x; acc[0][1] += a0 * bv.y; acc[0][2] += a0 * bv.z; acc[0][3] += a0 * bv.w;
        acc[1][0] += a1 * bv.x; acc[1][1] += a1 * bv.y; acc[1][2] += a1 * bv.z; acc[1][3] += a1 * bv.w;
        acc[2][0] += a2 * bv.x; acc[2][1] += a2 * bv.y; acc[2][2] += a2 * bv.z; acc[2][3] += a2 * bv.w;
        acc[3][0] += a3 * bv.x; acc[3][1] += a3 * bv.y; acc[3][2] += a3 * bv.z; acc[3][3] += a3 * bv.w;
    }
    float4 bb = ((const float4*)b)[tx];
#pragma unroll
    for (int i = 0; i < 4; i++) {
        int gr = row0 + ty * 4 + i;
        if (gr < n) {
            float4 o;
            o.x = fmaxf(acc[i][0] + bb.x, 0.f);
            o.y = fmaxf(acc[i][1] + bb.y, 0.f);
            o.z = fmaxf(acc[i][2] + bb.z, 0.f);
            o.w = fmaxf(acc[i][3] + bb.w, 0.f);
            ((float4*)(g_h + (size_t)gr * 128))[tx] = o;
        }
    }
}

// GEMM2: g_h2 = g_h @ W2     [n x 128] @ [128 x 64]
__global__ void gemm2_k(const float* __restrict__ W, int n) {
    extern __shared__ float sm[];
    float* ws = sm;           // 128*64 = 8192 floats
    float* xs = sm + 8192;    // 64*128 = 8192 floats
    int tid = threadIdx.x;
    for (int i = tid; i < 2048; i += 256)
        ((float4*)ws)[i] = ((const float4*)W)[i];
    int row0 = blockIdx.x * 64;
    for (int i = tid; i < 2048; i += 256) {
        int r = i >> 5, c = i & 31;
        int gr = row0 + r;
        float4 v = (gr < n) ? ((const float4*)(g_h + (size_t)gr * 128))[c]
                            : make_float4(0.f, 0.f, 0.f, 0.f);
        ((float4*)xs)[i] = v;
    }
    __syncthreads();
    int tx = tid & 15, ty = tid >> 4;
    float acc[4][4] = {};
    const float* x0 = xs + ty * 4 * 128;
#pragma unroll 4
    for (int k = 0; k < 128; k++) {
        float4 bv = ((const float4*)(ws + k * 64))[tx];
        float a0 = x0[k], a1 = x0[128 + k], a2 = x0[256 + k], a3 = x0[384 + k];
        acc[0][0] += a0 * bv.x; acc[0][1] += a0 * bv.y; acc[0][2] += a0 * bv.z; acc[0][3] += a0 * bv.w;
        acc[1][0] += a1 * bv.x; acc[1][1] += a1 * bv.y; acc[1][2] += a1 * bv.z; acc[1][3] += a1 * bv.w;
        acc[2][0] += a2 * bv.x; acc[2][1] += a2 * bv.y; acc[2][2] += a2 * bv.z; acc[2][3] += a2 * bv.w;
        acc[3][0] += a3 * bv.x; acc[3][1] += a3 * bv.y; acc[3][2] += a3 * bv.z; acc[3][3] += a3 * bv.w;
    }
#pragma unroll
    for (int i = 0; i < 4; i++) {
        int gr = row0 + ty * 4 + i;
        if (gr < n) {
            float4 h2v = make_float4(acc[i][0], acc[i][1], acc[i][2], acc[i][3]);
            ((float4*)(g_h2 + (size_t)gr * 64))[tx] = h2v;
        }
    }
}

extern "C" void kernel_launch(void* const* d_in, const int* in_sizes, int n_in,
                              void* d_out, int out_size) {
    const float* x   = (const float*)d_in[0];
    const int*   ei  = (const int*)d_in[1];   // int32 (JAX x64 disabled)
    const float* W1  = (const float*)d_in[2];
    const float* b1  = (const float*)d_in[3];
    const float* W2  = (const float*)d_in[4];
    const float* b2  = (const float*)d_in[5];
    float* out       = (float*)d_out;

    int n = in_sizes[0] / IND;
    int E = in_sizes[1] / 2;
    const int* src = ei;
    const int* dst = ei + E;

    cudaFuncSetAttribute(gemm1_k, cudaFuncAttributeMaxDynamicSharedMemorySize, 20480 * 4);
    cudaFuncSetAttribute(gemm2_k, cudaFuncAttributeMaxDynamicSharedMemorySize, 16384 * 4);

    const int TB = 256;
    // CSR build: deg -> dinv + scan -> scatter
    zero_deg_k<<<(n + TB - 1) / TB, TB>>>(n);
    deg_k<<<(E + TB - 1) / TB, TB>>>(dst, E);
    dinv_k<<<(n + TB - 1) / TB, TB>>>(n);
    scan_k<<<1, 1024>>>(n);
    scatter_k<<<(E + TB - 1) / TB, TB>>>(src, dst, E);
    // layer 1: CSR-aggregate x (with self-loop), then GEMM+bias+relu
    int aggBlocks = (int)(((long long)n * 32 + TB - 1) / TB);
    agg1_k<<<aggBlocks, TB>>>(x, n);
    gemm1_k<<<(n + 31) / 32, TB, 20480 * 4>>>(W1, b1, n);
    // layer 2: GEMM first, then CSR-aggregate 64-d (with self-loop + bias)
    gemm2_k<<<(n + 63) / 64, TB, 16384 * 4>>>(W2, n);
    agg2_k<<<aggBlocks, TB>>>(b2, out, n);
}

// round 4
// speedup vs baseline: 1.5824x; 1.4646x over previous
#include <cuda_runtime.h>

#define NMAX 100000
#define EMAX 1600000
#define IND 128
#define HID 128
#define OUTD 64
#define SCAN_B 1024
#define MAXBLK 128   // ceil(NMAX/SCAN_B) = 98 <= 128

// Scratch (static __device__ — allocation-free per harness rules)
__device__ int   g_degc[NMAX];
__device__ float g_dinv[NMAX];
__device__ int   g_rowptr[NMAX + 1];
__device__ int   g_pos[NMAX];
__device__ int   g_csr_src[EMAX];
__device__ int   g_blocksum[MAXBLK];
__device__ int   g_blockoff[MAXBLK];
__device__ float g_aggx[(size_t)NMAX * IND];   // aggregated x (layer-1 pre-GEMM)
__device__ float g_h[(size_t)NMAX * HID];      // relu(aggx@W1+b1)
__device__ float g_h2[(size_t)NMAX * OUTD];    // h@W2 (pre-aggregation)

__global__ void zero_deg_k(int n) {
    int i = blockIdx.x * blockDim.x + threadIdx.x;
    if (i < n) g_degc[i] = 0;
}

__global__ void deg_k(const int* __restrict__ dst, int E) {
    int i = blockIdx.x * blockDim.x + threadIdx.x;
    if (i < E) atomicAdd(&g_degc[dst[i]], 1);
}

__global__ void dinv_k(int n) {
    int i = blockIdx.x * blockDim.x + threadIdx.x;
    if (i < n) g_dinv[i] = rsqrtf((float)g_degc[i] + 1.0f);
}

// ---- 3-phase parallel exclusive scan of g_degc -> g_rowptr / g_pos ----

__global__ void blocksum_k(int n) {
    __shared__ int red[32];
    int i = blockIdx.x * SCAN_B + threadIdx.x;
    int v = (i < n) ? g_degc[i] : 0;
    int lane = threadIdx.x & 31, w = threadIdx.x >> 5;
#pragma unroll
    for (int o = 16; o > 0; o >>= 1) v += __shfl_down_sync(0xffffffffu, v, o);
    if (lane == 0) red[w] = v;
    __syncthreads();
    if (w == 0) {
        int s = red[lane];
#pragma unroll
        for (int o = 16; o > 0; o >>= 1) s += __shfl_down_sync(0xffffffffu, s, o);
        if (lane == 0) g_blocksum[blockIdx.x] = s;
    }
}

// Single small block: exclusive scan of nb (<=128) block sums.
__global__ void scanblocks_k(int nb) {
    __shared__ int ws[4];
    int t = threadIdx.x;               // 128 threads
    int lane = t & 31, w = t >> 5;
    int v = (t < nb) ? g_blocksum[t] : 0;
    int x = v;
#pragma unroll
    for (int o = 1; o < 32; o <<= 1) {
        int y = __shfl_up_sync(0xffffffffu, x, o);
        if (lane >= o) x += y;
    }
    if (lane == 31) ws[w] = x;
    __syncthreads();
    if (w == 0 && lane < 4) {
        int s = ws[lane];
#pragma unroll
        for (int o = 1; o < 4; o <<= 1) {
            int y = __shfl_up_sync(0x0000000fu, s, o);
            if (lane >= o) s += y;
        }
        ws[lane] = s;
    }
    __syncthreads();
    int incl = x + (w > 0 ? ws[w - 1] : 0);
    if (t < nb) g_blockoff[t] = incl - v;   // exclusive
}

// Per-block exclusive scan + block offset -> rowptr, pos.
__global__ void scanfinal_k(int n) {
    __shared__ int wsum[32];
    int b = blockIdx.x;
    int t = threadIdx.x;
    int i = b * SCAN_B + t;
    int v = (i < n) ? g_degc[i] : 0;
    int lane = t & 31, w = t >> 5;
    int x = v;
#pragma unroll
    for (int o = 1; o < 32; o <<= 1) {
        int y = __shfl_up_sync(0xffffffffu, x, o);
        if (lane >= o) x += y;
    }
    if (lane == 31) wsum[w] = x;
    __syncthreads();
    if (w == 0) {
        int s = wsum[lane];
#pragma unroll
        for (int o = 1; o < 32; o <<= 1) {
            int y = __shfl_up_sync(0xffffffffu, s, o);
            if (lane >= o) s += y;
        }
        wsum[lane] = s;
    }
    __syncthreads();
    int incl = x + (w > 0 ? wsum[w - 1] : 0);
    int excl = incl - v + g_blockoff[b];
    if (i < n) {
        g_rowptr[i] = excl;
        g_pos[i] = excl;
        if (i == n - 1) g_rowptr[n] = excl + v;
    }
}

// Scatter src ids into dst-sorted CSR slots.
__global__ void scatter_k(const int* __restrict__ src,
                          const int* __restrict__ dst, int E) {
    int e = blockIdx.x * blockDim.x + threadIdx.x;
    if (e < E) {
        int d = dst[e];
        int p = atomicAdd(&g_pos[d], 1);
        g_csr_src[p] = src[e];
    }
}

// Layer-1 aggregation (CSR, warp per dst node, 128-d):
// aggx[i] = x[i]*dinv[i]^2 + sum_j x[src_j] * dinv[src_j]*dinv[i]
__global__ void agg1_k(const float* __restrict__ x, int n) {
    int w = (blockIdx.x * blockDim.x + threadIdx.x) >> 5;
    if (w >= n) return;
    int c = threadIdx.x & 31;
    float di = g_dinv[w];
    float d2 = di * di;
    float4 acc = ((const float4*)(x + (size_t)w * IND))[c];
    acc.x *= d2; acc.y *= d2; acc.z *= d2; acc.w *= d2;
    int j = g_rowptr[w], end = g_rowptr[w + 1];
    for (; j + 1 < end; j += 2) {
        int s0 = __ldg(&g_csr_src[j]);
        int s1 = __ldg(&g_csr_src[j + 1]);
        float nm0 = __ldg(&g_dinv[s0]) * di;
        float nm1 = __ldg(&g_dinv[s1]) * di;
        float4 v0 = __ldg((const float4*)(x + (size_t)s0 * IND) + c);
        float4 v1 = __ldg((const float4*)(x + (size_t)s1 * IND) + c);
        acc.x += v0.x * nm0; acc.y += v0.y * nm0; acc.z += v0.z * nm0; acc.w += v0.w * nm0;
        acc.x += v1.x * nm1; acc.y += v1.y * nm1; acc.z += v1.z * nm1; acc.w += v1.w * nm1;
    }
    if (j < end) {
        int s = __ldg(&g_csr_src[j]);
        float nm = __ldg(&g_dinv[s]) * di;
        float4 v = __ldg((const float4*)(x + (size_t)s * IND) + c);
        acc.x += v.x * nm; acc.y += v.y * nm; acc.z += v.z * nm; acc.w += v.w * nm;
    }
    ((float4*)(g_aggx + (size_t)w * IND))[c] = acc;
}

// Layer-2 aggregation (CSR, warp per dst node, 64-d, float2 per lane):
// out[i] = h2[i]*dinv[i]^2 + b2 + sum_j h2[src_j]*dinv[src_j]*dinv[i]
__global__ void agg2_k(const float* __restrict__ b2,
                       float* __restrict__ out, int n) {
    int w = (blockIdx.x * blockDim.x + threadIdx.x) >> 5;
    if (w >= n) return;
    int c = threadIdx.x & 31;
    float di = g_dinv[w];
    float d2 = di * di;
    float2 bb = ((const float2*)b2)[c];
    float2 self = ((const float2*)(g_h2 + (size_t)w * OUTD))[c];
    float2 acc;
    acc.x = self.x * d2 + bb.x;
    acc.y = self.y * d2 + bb.y;
    int j = g_rowptr[w], end = g_rowptr[w + 1];
    for (; j + 1 < end; j += 2) {
        int s0 = __ldg(&g_csr_src[j]);
        int s1 = __ldg(&g_csr_src[j + 1]);
        float nm0 = __ldg(&g_dinv[s0]) * di;
        float nm1 = __ldg(&g_dinv[s1]) * di;
        float2 v0 = __ldg((const float2*)(g_h2 + (size_t)s0 * OUTD) + c);
        float2 v1 = __ldg((const float2*)(g_h2 + (size_t)s1 * OUTD) + c);
        acc.x += v0.x * nm0; acc.y += v0.y * nm0;
        acc.x += v1.x * nm1; acc.y += v1.y * nm1;
    }
    if (j < end) {
        int s = __ldg(&g_csr_src[j]);
        float nm = __ldg(&g_dinv[s]) * di;
        float2 v = __ldg((const float2*)(g_h2 + (size_t)s * OUTD) + c);
        acc.x += v.x * nm; acc.y += v.y * nm;
    }
    ((float2*)(out + (size_t)w * OUTD))[c] = acc;
}

// GEMM1: g_h = relu(g_aggx @ W1 + b1)     [n x 128] @ [128 x 128]
__global__ void gemm1_k(const float* __restrict__ W, const float* __restrict__ b, int n) {
    extern __shared__ float sm[];
    float* ws = sm;            // 128*128 = 16384 floats
    float* xs = sm + 16384;    // 32*128  = 4096 floats
    int tid = threadIdx.x;
    for (int i = tid; i < 4096; i += 256)
        ((float4*)ws)[i] = ((const float4*)W)[i];
    int row0 = blockIdx.x * 32;
    for (int i = tid; i < 1024; i += 256) {
        int r = i >> 5, c = i & 31;
        int gr = row0 + r;
        float4 v = (gr < n) ? ((const float4*)(g_aggx + (size_t)gr * 128))[c]
                            : make_float4(0.f, 0.f, 0.f, 0.f);
        ((float4*)xs)[i] = v;
    }
    __syncthreads();
    int tx = tid & 31, ty = tid >> 5;
    float acc[4][4] = {};
    const float* x0 = xs + ty * 4 * 128;
#pragma unroll 4
    for (int k = 0; k < 128; k++) {
        float4 bv = ((const float4*)(ws + k * 128))[tx];
        float a0 = x0[k], a1 = x0[128 + k], a2 = x0[256 + k], a3 = x0[384 + k];
        acc[0][0] += a0 * bv.x; acc[0][1] += a0 * bv.y; acc[0][2] += a0 * bv.z; acc[0][3] += a0 * bv.w;
        acc[1][0] += a1 * bv.x; acc[1][1] += a1 * bv.y; acc[1][2] += a1 * bv.z; acc[1][3] += a1 * bv.w;
        acc[2][0] += a2 * bv.x; acc[2][1] += a2 * bv.y; acc[2][2] += a2 * bv.z; acc[2][3] += a2 * bv.w;
        acc[3][0] += a3 * bv.x; acc[3][1] += a3 * bv.y; acc[3][2] += a3 * bv.z; acc[3][3] += a3 * bv.w;
    }
    float4 bb = ((const float4*)b)[tx];
#pragma unroll
    for (int i = 0; i < 4; i++) {
        int gr = row0 + ty * 4 + i;
        if (gr < n) {
            float4 o;
            o.x = fmaxf(acc[i][0] + bb.x, 0.f);
            o.y = fmaxf(acc[i][1] + bb.y, 0.f);
            o.z = fmaxf(acc[i][2] + bb.z, 0.f);
            o.w = fmaxf(acc[i][3] + bb.w, 0.f);
            ((float4*)(g_h + (size_t)gr * 128))[tx] = o;
        }
    }
}

// GEMM2: g_h2 = g_h @ W2     [n x 128] @ [128 x 64]
__global__ void gemm2_k(const float* __restrict__ W, int n) {
    extern __shared__ float sm[];
    float* ws = sm;           // 128*64 = 8192 floats
    float* xs = sm + 8192;    // 64*128 = 8192 floats
    int tid = threadIdx.x;
    for (int i = tid; i < 2048; i += 256)
        ((float4*)ws)[i] = ((const float4*)W)[i];
    int row0 = blockIdx.x * 64;
    for (int i = tid; i < 2048; i += 256) {
        int r = i >> 5, c = i & 31;
        int gr = row0 + r;
        float4 v = (gr < n) ? ((const float4*)(g_h + (size_t)gr * 128))[c]
                            : make_float4(0.f, 0.f, 0.f, 0.f);
        ((float4*)xs)[i] = v;
    }
    __syncthreads();
    int tx = tid & 15, ty = tid >> 4;
    float acc[4][4] = {};
    const float* x0 = xs + ty * 4 * 128;
#pragma unroll 4
    for (int k = 0; k < 128; k++) {
        float4 bv = ((const float4*)(ws + k * 64))[tx];
        float a0 = x0[k], a1 = x0[128 + k], a2 = x0[256 + k], a3 = x0[384 + k];
        acc[0][0] += a0 * bv.x; acc[0][1] += a0 * bv.y; acc[0][2] += a0 * bv.z; acc[0][3] += a0 * bv.w;
        acc[1][0] += a1 * bv.x; acc[1][1] += a1 * bv.y; acc[1][2] += a1 * bv.z; acc[1][3] += a1 * bv.w;
        acc[2][0] += a2 * bv.x; acc[2][1] += a2 * bv.y; acc[2][2] += a2 * bv.z; acc[2][3] += a2 * bv.w;
        acc[3][0] += a3 * bv.x; acc[3][1] += a3 * bv.y; acc[3][2] += a3 * bv.z; acc[3][3] += a3 * bv.w;
    }
#pragma unroll
    for (int i = 0; i < 4; i++) {
        int gr = row0 + ty * 4 + i;
        if (gr < n) {
            float4 h2v = make_float4(acc[i][0], acc[i][1], acc[i][2], acc[i][3]);
            ((float4*)(g_h2 + (size_t)gr * 64))[tx] = h2v;
        }
    }
}

extern "C" void kernel_launch(void* const* d_in, const int* in_sizes, int n_in,
                              void* d_out, int out_size) {
    const float* x   = (const float*)d_in[0];
    const int*   ei  = (const int*)d_in[1];   // int32 (JAX x64 disabled)
    const float* W1  = (const float*)d_in[2];
    const float* b1  = (const float*)d_in[3];
    const float* W2  = (const float*)d_in[4];
    const float* b2  = (const float*)d_in[5];
    float* out       = (float*)d_out;

    int n = in_sizes[0] / IND;
    int E = in_sizes[1] / 2;
    const int* src = ei;
    const int* dst = ei + E;

    cudaFuncSetAttribute(gemm1_k, cudaFuncAttributeMaxDynamicSharedMemorySize, 20480 * 4);
    cudaFuncSetAttribute(gemm2_k, cudaFuncAttributeMaxDynamicSharedMemorySize, 16384 * 4);

    const int TB = 256;
    int nb = (n + SCAN_B - 1) / SCAN_B;   // scan blocks (98 for n=100k)
    // CSR build: deg -> dinv, 3-phase scan, scatter
    zero_deg_k<<<(n + TB - 1) / TB, TB>>>(n);
    deg_k<<<(E + TB - 1) / TB, TB>>>(dst, E);
    dinv_k<<<(n + TB - 1) / TB, TB>>>(n);
    blocksum_k<<<nb, SCAN_B>>>(n);
    scanblocks_k<<<1, 128>>>(nb);
    scanfinal_k<<<nb, SCAN_B>>>(n);
    scatter_k<<<(E + TB - 1) / TB, TB>>>(src, dst, E);
    // layer 1: CSR-aggregate x (with self-loop), then GEMM+bias+relu
    int aggBlocks = (int)(((long long)n * 32 + TB - 1) / TB);
    agg1_k<<<aggBlocks, TB>>>(x, n);
    gemm1_k<<<(n + 31) / 32, TB, 20480 * 4>>>(W1, b1, n);
    // layer 2: GEMM first, then CSR-aggregate 64-d (with self-loop + bias)
    gemm2_k<<<(n + 63) / 64, TB, 16384 * 4>>>(W2, n);
    agg2_k<<<aggBlocks, TB>>>(b2, out, n);
}

// round 6
// speedup vs baseline: 1.9421x; 1.2273x over previous
#include <cuda_runtime.h>
#include <cuda_fp16.h>
#include <cstdint>

#define NMAX 100000
#define EMAX 1600000
#define IND 128
#define HID 128
#define OUTD 64
#define SCAN_B 1024
#define MAXBLK 128

// ---------------- scratch (static __device__, allocation-free) ----------------
__device__ int   g_degc[NMAX];
__device__ float g_dinv[NMAX];
__device__ int   g_rowptr[NMAX + 1];
__device__ int   g_pos[NMAX];
__device__ int   g_csr_src[EMAX];
__device__ int   g_blocksum[MAXBLK];
__device__ int   g_blockoff[MAXBLK];
__device__ float g_aggx[(size_t)NMAX * IND];
__device__ float g_h[(size_t)NMAX * HID];
__device__ float g_h2[(size_t)NMAX * OUTD];
// W pre-transposed to [n][k] f16 hi/lo (hi + lo == fp32 weight to ~2^-22)
__device__ __half g_w1hi[HID * IND];
__device__ __half g_w1lo[HID * IND];
__device__ __half g_w2hi[OUTD * IND];
__device__ __half g_w2lo[OUTD * IND];

__device__ __forceinline__ uint32_t smem_u32(const void* p) {
    uint32_t a;
    asm("{ .reg .u64 t; cvta.to.shared.u64 t, %1; cvt.u32.u64 %0, t; }" : "=r"(a) : "l"(p));
    return a;
}
__device__ __forceinline__ void ldm_x4(uint32_t* r, uint32_t addr) {
    asm volatile("ldmatrix.sync.aligned.m8n8.x4.shared.b16 {%0,%1,%2,%3}, [%4];"
                 : "=r"(r[0]), "=r"(r[1]), "=r"(r[2]), "=r"(r[3]) : "r"(addr));
}
__device__ __forceinline__ void mma16816(float* d, const uint32_t* a, const uint32_t* b) {
    asm volatile(
        "mma.sync.aligned.m16n8k16.row.col.f32.f16.f16.f32 "
        "{%0,%1,%2,%3}, {%4,%5,%6,%7}, {%8,%9}, {%0,%1,%2,%3};"
        : "+f"(d[0]), "+f"(d[1]), "+f"(d[2]), "+f"(d[3])
        : "r"(a[0]), "r"(a[1]), "r"(a[2]), "r"(a[3]), "r"(b[0]), "r"(b[1]));
}
__device__ __forceinline__ void split_h(float v, __half& hi, __half& lo) {
    hi = __float2half_rn(v);
    lo = __float2half_rn(v - __half2float(hi));
}

// ---------------- CSR build ----------------
__global__ void zero_deg_k(int n) {
    int i = blockIdx.x * blockDim.x + threadIdx.x;
    if (i < n) g_degc[i] = 0;
}
__global__ void deg_k(const int* __restrict__ dst, int E) {
    int i = blockIdx.x * blockDim.x + threadIdx.x;
    if (i < E) atomicAdd(&g_degc[dst[i]], 1);
}
__global__ void dinv_k(int n) {
    int i = blockIdx.x * blockDim.x + threadIdx.x;
    if (i < n) g_dinv[i] = rsqrtf((float)g_degc[i] + 1.0f);
}
__global__ void blocksum_k(int n) {
    __shared__ int red[32];
    int i = blockIdx.x * SCAN_B + threadIdx.x;
    int v = (i < n) ? g_degc[i] : 0;
    int lane = threadIdx.x & 31, w = threadIdx.x >> 5;
#pragma unroll
    for (int o = 16; o > 0; o >>= 1) v += __shfl_down_sync(0xffffffffu, v, o);
    if (lane == 0) red[w] = v;
    __syncthreads();
    if (w == 0) {
        int s = red[lane];
#pragma unroll
        for (int o = 16; o > 0; o >>= 1) s += __shfl_down_sync(0xffffffffu, s, o);
        if (lane == 0) g_blocksum[blockIdx.x] = s;
    }
}
__global__ void scanblocks_k(int nb) {
    __shared__ int ws[4];
    int t = threadIdx.x;
    int lane = t & 31, w = t >> 5;
    int v = (t < nb) ? g_blocksum[t] : 0;
    int x = v;
#pragma unroll
    for (int o = 1; o < 32; o <<= 1) {
        int y = __shfl_up_sync(0xffffffffu, x, o);
        if (lane >= o) x += y;
    }
    if (lane == 31) ws[w] = x;
    __syncthreads();
    if (w == 0 && lane < 4) {
        int s = ws[lane];
#pragma unroll
        for (int o = 1; o < 4; o <<= 1) {
            int y = __shfl_up_sync(0x0000000fu, s, o);
            if (lane >= o) s += y;
        }
        ws[lane] = s;
    }
    __syncthreads();
    int incl = x + (w > 0 ? ws[w - 1] : 0);
    if (t < nb) g_blockoff[t] = incl - v;
}
__global__ void scanfinal_k(int n) {
    __shared__ int wsum[32];
    int b = blockIdx.x, t = threadIdx.x;
    int i = b * SCAN_B + t;
    int v = (i < n) ? g_degc[i] : 0;
    int lane = t & 31, w = t >> 5;
    int x = v;
#pragma unroll
    for (int o = 1; o < 32; o <<= 1) {
        int y = __shfl_up_sync(0xffffffffu, x, o);
        if (lane >= o) x += y;
    }
    if (lane == 31) wsum[w] = x;
    __syncthreads();
    if (w == 0) {
        int s = wsum[lane];
#pragma unroll
        for (int o = 1; o < 32; o <<= 1) {
            int y = __shfl_up_sync(0xffffffffu, s, o);
            if (lane >= o) s += y;
        }
        wsum[lane] = s;
    }
    __syncthreads();
    int incl = x + (w > 0 ? wsum[w - 1] : 0);
    int excl = incl - v + g_blockoff[b];
    if (i < n) {
        g_rowptr[i] = excl;
        g_pos[i] = excl;
        if (i == n - 1) g_rowptr[n] = excl + v;
    }
}
__global__ void scatter_k(const int* __restrict__ src, const int* __restrict__ dst, int E) {
    int e = blockIdx.x * blockDim.x + threadIdx.x;
    if (e < E) {
        int p = atomicAdd(&g_pos[dst[e]], 1);
        g_csr_src[p] = src[e];
    }
}

// ---------------- aggregation (CSR, warp per dst) ----------------
__global__ void agg1_k(const float* __restrict__ x, int n) {
    int w = (blockIdx.x * blockDim.x + threadIdx.x) >> 5;
    if (w >= n) return;
    int c = threadIdx.x & 31;
    float di = g_dinv[w];
    float d2 = di * di;
    float4 acc = ((const float4*)(x + (size_t)w * IND))[c];
    acc.x *= d2; acc.y *= d2; acc.z *= d2; acc.w *= d2;
    int j = g_rowptr[w], end = g_rowptr[w + 1];
    for (; j + 1 < end; j += 2) {
        int s0 = __ldg(&g_csr_src[j]);
        int s1 = __ldg(&g_csr_src[j + 1]);
        float nm0 = __ldg(&g_dinv[s0]) * di;
        float nm1 = __ldg(&g_dinv[s1]) * di;
        float4 v0 = __ldg((const float4*)(x + (size_t)s0 * IND) + c);
        float4 v1 = __ldg((const float4*)(x + (size_t)s1 * IND) + c);
        acc.x += v0.x * nm0; acc.y += v0.y * nm0; acc.z += v0.z * nm0; acc.w += v0.w * nm0;
        acc.x += v1.x * nm1; acc.y += v1.y * nm1; acc.z += v1.z * nm1; acc.w += v1.w * nm1;
    }
    if (j < end) {
        int s = __ldg(&g_csr_src[j]);
        float nm = __ldg(&g_dinv[s]) * di;
        float4 v = __ldg((const float4*)(x + (size_t)s * IND) + c);
        acc.x += v.x * nm; acc.y += v.y * nm; acc.z += v.z * nm; acc.w += v.w * nm;
    }
    ((float4*)(g_aggx + (size_t)w * IND))[c] = acc;
}

__global__ void agg2_k(const float* __restrict__ b2, float* __restrict__ out, int n) {
    int w = (blockIdx.x * blockDim.x + threadIdx.x) >> 5;
    if (w >= n) return;
    int c = threadIdx.x & 31;
    float di = g_dinv[w];
    float d2 = di * di;
    float2 bb = ((const float2*)b2)[c];
    float2 self = ((const float2*)(g_h2 + (size_t)w * OUTD))[c];
    float2 acc;
    acc.x = self.x * d2 + bb.x;
    acc.y = self.y * d2 + bb.y;
    int j = g_rowptr[w], end = g_rowptr[w + 1];
    for (; j + 1 < end; j += 2) {
        int s0 = __ldg(&g_csr_src[j]);
        int s1 = __ldg(&g_csr_src[j + 1]);
        float nm0 = __ldg(&g_dinv[s0]) * di;
        float nm1 = __ldg(&g_dinv[s1]) * di;
        float2 v0 = __ldg((const float2*)(g_h2 + (size_t)s0 * OUTD) + c);
        float2 v1 = __ldg((const float2*)(g_h2 + (size_t)s1 * OUTD) + c);
        acc.x += v0.x * nm0; acc.y += v0.y * nm0;
        acc.x += v1.x * nm1; acc.y += v1.y * nm1;
    }
    if (j < end) {
        int s = __ldg(&g_csr_src[j]);
        float nm = __ldg(&g_dinv[s]) * di;
        float2 v = __ldg((const float2*)(g_h2 + (size_t)s * OUTD) + c);
        acc.x += v.x * nm; acc.y += v.y * nm;
    }
    ((float2*)(out + (size_t)w * OUTD))[c] = acc;
}

// ---------------- W prep: hi/lo split, transpose to [n][k] ----------------
__global__ void w1prep_k(const float* __restrict__ W1) {
    int i = blockIdx.x * blockDim.x + threadIdx.x;  // 16384
    if (i >= HID * IND) return;
    int nn = i & 127, k = i >> 7;
    float w = W1[k * HID + nn];
    __half hi, lo; split_h(w, hi, lo);
    g_w1hi[nn * IND + k] = hi;
    g_w1lo[nn * IND + k] = lo;
}
__global__ void w2prep_k(const float* __restrict__ W2) {
    int i = blockIdx.x * blockDim.x + threadIdx.x;  // 8192
    if (i >= OUTD * IND) return;
    int nn = i & 63, k = i >> 6;
    float w = W2[k * OUTD + nn];
    __half hi, lo; split_h(w, hi, lo);
    g_w2hi[nn * IND + k] = hi;
    g_w2lo[nn * IND + k] = lo;
}

// ---------------- HMMA GEMMs (mma.sync m16n8k16, fp16 hi/lo x 3 passes) ----------------
// smem layout halves, padded row stride 136 (272B: conflict-free ldmatrix)
#define LDA 136

// GEMM1: g_h = relu(g_aggx @ W1 + b1);  block = 128 rows x 128 cols, 8 warps.
__global__ __launch_bounds__(256, 1) void gemm1_mma(const float* __restrict__ b1, int n) {
    extern __shared__ __half sm[];
    __half* Ah = sm;                    // 128*136
    __half* Al = Ah + 128 * LDA;
    __half* Bh = Al + 128 * LDA;        // 128*136 ([n][k])
    __half* Bl = Bh + 128 * LDA;
    int tid = threadIdx.x, wid = tid >> 5, lane = tid & 31;
    int r0 = blockIdx.x * 128;

    // A: load + split
    for (int i = tid; i < 4096; i += 256) {
        int row = i >> 5, c = i & 31;           // c: float4 index (4 floats)
        int gr = r0 + row;
        float4 v = (gr < n) ? ((const float4*)(g_aggx + (size_t)gr * IND))[c]
                            : make_float4(0.f, 0.f, 0.f, 0.f);
        __half h0, h1, h2, h3, l0, l1, l2, l3;
        split_h(v.x, h0, l0); split_h(v.y, h1, l1);
        split_h(v.z, h2, l2); split_h(v.w, h3, l3);
        int o = row * LDA + c * 4;
        *(__half2*)(Ah + o) = __halves2half2(h0, h1);
        *(__half2*)(Ah + o + 2) = __halves2half2(h2, h3);
        *(__half2*)(Al + o) = __halves2half2(l0, l1);
        *(__half2*)(Al + o + 2) = __halves2half2(l2, l3);
    }
    // B: copy pre-split W ([n][k] linear -> padded)
    for (int i = tid; i < 2048; i += 256) {     // uint4 = 8 halves
        int row = i >> 4, seg = i & 15;
        *(uint4*)(Bh + row * LDA + seg * 8) = ((const uint4*)g_w1hi)[i];
        *(uint4*)(Bl + row * LDA + seg * 8) = ((const uint4*)g_w1lo)[i];
    }
    __syncthreads();

    // per-lane ldmatrix addresses
    uint32_t ah_b = smem_u32(Ah), al_b = smem_u32(Al);
    uint32_t bh_b = smem_u32(Bh), bl_b = smem_u32(Bl);
    int a_row = wid * 16 + (lane & 15);
    int a_co = (lane >> 4) * 8;
    uint32_t a_off = (uint32_t)(a_row * LDA + a_co) * 2;
    int b_row = (lane & 7) + ((lane >> 4) << 3);
    int b_co = ((lane >> 3) & 1) * 8;
    uint32_t b_off = (uint32_t)(b_row * LDA + b_co) * 2;

    float acc[16][4];
#pragma unroll
    for (int t = 0; t < 16; t++)
#pragma unroll
        for (int j = 0; j < 4; j++) acc[t][j] = 0.f;

#pragma unroll
    for (int ks = 0; ks < 8; ks++) {
        uint32_t ahr[4], alr[4];
        ldm_x4(ahr, ah_b + a_off + ks * 32);   // 16 halves = 32B per kstep
        ldm_x4(alr, al_b + a_off + ks * 32);
#pragma unroll
        for (int np = 0; np < 8; np++) {
            uint32_t bhr[4], blr[4];
            uint32_t bo = b_off + (uint32_t)(np * 16 * LDA * 2) + ks * 32;
            ldm_x4(bhr, bh_b + bo);
            ldm_x4(blr, bl_b + bo);
            mma16816(acc[2 * np], ahr, bhr);
            mma16816(acc[2 * np], ahr, blr);
            mma16816(acc[2 * np], alr, bhr);
            mma16816(acc[2 * np + 1], ahr, bhr + 2);
            mma16816(acc[2 * np + 1], ahr, blr + 2);
            mma16816(acc[2 * np + 1], alr, bhr + 2);
        }
    }

    // epilogue: bias + relu, direct fragment stores
    int grp = lane >> 2, qid = lane & 3;
    int rowA = r0 + wid * 16 + grp;
    int rowB = rowA + 8;
#pragma unroll
    for (int t = 0; t < 16; t++) {
        int col = t * 8 + qid * 2;
        float2 bb = *(const float2*)(b1 + col);
        if (rowA < n) {
            float2 o = make_float2(fmaxf(acc[t][0] + bb.x, 0.f),
                                   fmaxf(acc[t][1] + bb.y, 0.f));
            *(float2*)(g_h + (size_t)rowA * HID + col) = o;
        }
        if (rowB < n) {
            float2 o = make_float2(fmaxf(acc[t][2] + bb.x, 0.f),
                                   fmaxf(acc[t][3] + bb.y, 0.f));
            *(float2*)(g_h + (size_t)rowB * HID + col) = o;
        }
    }
}

// GEMM2: g_h2 = g_h @ W2;  block = 128 rows x 64 cols, 8 warps.
__global__ __launch_bounds__(256, 1) void gemm2_mma(int n) {
    extern __shared__ __half sm[];
    __half* Ah = sm;                    // 128*136
    __half* Al = Ah + 128 * LDA;
    __half* Bh = Al + 128 * LDA;        // 64*136
    __half* Bl = Bh + 64 * LDA;
    int tid = threadIdx.x, wid = tid >> 5, lane = tid & 31;
    int r0 = blockIdx.x * 128;

    for (int i = tid; i < 4096; i += 256) {
        int row = i >> 5, c = i & 31;
        int gr = r0 + row;
        float4 v = (gr < n) ? ((const float4*)(g_h + (size_t)gr * HID))[c]
                            : make_float4(0.f, 0.f, 0.f, 0.f);
        __half h0, h1, h2, h3, l0, l1, l2, l3;
        split_h(v.x, h0, l0); split_h(v.y, h1, l1);
        split_h(v.z, h2, l2); split_h(v.w, h3, l3);
        int o = row * LDA + c * 4;
        *(__half2*)(Ah + o) = __halves2half2(h0, h1);
        *(__half2*)(Ah + o + 2) = __halves2half2(h2, h3);
        *(__half2*)(Al + o) = __halves2half2(l0, l1);
        *(__half2*)(Al + o + 2) = __halves2half2(l2, l3);
    }
    for (int i = tid; i < 1024; i += 256) {
        int row = i >> 4, seg = i & 15;
        *(uint4*)(Bh + row * LDA + seg * 8) = ((const uint4*)g_w2hi)[i];
        *(uint4*)(Bl + row * LDA + seg * 8) = ((const uint4*)g_w2lo)[i];
    }
    __syncthreads();

    uint32_t ah_b = smem_u32(Ah), al_b = smem_u32(Al);
    uint32_t bh_b = smem_u32(Bh), bl_b = smem_u32(Bl);
    int a_row = wid * 16 + (lane & 15);
    int a_co = (lane >> 4) * 8;
    uint32_t a_off = (uint32_t)(a_row * LDA + a_co) * 2;
    int b_row = (lane & 7) + ((lane >> 4) << 3);
    int b_co = ((lane >> 3) & 1) * 8;
    uint32_t b_off = (uint32_t)(b_row * LDA + b_co) * 2;

    float acc[8][4];
#pragma unroll
    for (int t = 0; t < 8; t++)
#pragma unroll
        for (int j = 0; j < 4; j++) acc[t][j] = 0.f;

#pragma unroll
    for (int ks = 0; ks < 8; ks++) {
        uint32_t ahr[4], alr[4];
        ldm_x4(ahr, ah_b + a_off + ks * 32);
        ldm_x4(alr, al_b + a_off + ks * 32);
#pragma unroll
        for (int np = 0; np < 4; np++) {
            uint32_t bhr[4], blr[4];
            uint32_t bo = b_off + (uint32_t)(np * 16 * LDA * 2) + ks * 32;
            ldm_x4(bhr, bh_b + bo);
            ldm_x4(blr, bl_b + bo);
            mma16816(acc[2 * np], ahr, bhr);
            mma16816(acc[2 * np], ahr, blr);
            mma16816(acc[2 * np], alr, bhr);
            mma16816(acc[2 * np + 1], ahr, bhr + 2);
            mma16816(acc[2 * np + 1], ahr, blr + 2);
            mma16816(acc[2 * np + 1], alr, bhr + 2);
        }
    }

    int grp = lane >> 2, qid = lane & 3;
    int rowA = r0 + wid * 16 + grp;
    int rowB = rowA + 8;
#pragma unroll
    for (int t = 0; t < 8; t++) {
        int col = t * 8 + qid * 2;
        if (rowA < n)
            *(float2*)(g_h2 + (size_t)rowA * OUTD + col) = make_float2(acc[t][0], acc[t][1]);
        if (rowB < n)
            *(float2*)(g_h2 + (size_t)rowB * OUTD + col) = make_float2(acc[t][2], acc[t][3]);
    }
}

// ---------------- launch ----------------
extern "C" void kernel_launch(void* const* d_in, const int* in_sizes, int n_in,
                              void* d_out, int out_size) {
    const float* x  = (const float*)d_in[0];
    const int*   ei = (const int*)d_in[1];
    const float* W1 = (const float*)d_in[2];
    const float* b1 = (const float*)d_in[3];
    const float* W2 = (const float*)d_in[4];
    const float* b2 = (const float*)d_in[5];
    float* out      = (float*)d_out;

    int n = in_sizes[0] / IND;
    int E = in_sizes[1] / 2;
    const int* src = ei;
    const int* dst = ei + E;

    const int SM1 = (128 * LDA * 2 + 128 * LDA * 2) * 2;           // A(hi/lo)+B(hi/lo) = 139264B
    const int SM2 = (128 * LDA * 2) * 2 + (64 * LDA * 2) * 2;      // 104448B
    cudaFuncSetAttribute(gemm1_mma, cudaFuncAttributeMaxDynamicSharedMemorySize, SM1);
    cudaFuncSetAttribute(gemm2_mma, cudaFuncAttributeMaxDynamicSharedMemorySize, SM2);

    const int TB = 256;
    int nb = (n + SCAN_B - 1) / SCAN_B;
    int gblk = (n + 127) / 128;

    w1prep_k<<<(HID * IND + TB - 1) / TB, TB>>>(W1);
    w2prep_k<<<(OUTD * IND + TB - 1) / TB, TB>>>(W2);
    zero_deg_k<<<(n + TB - 1) / TB, TB>>>(n);
    deg_k<<<(E + TB - 1) / TB, TB>>>(dst, E);
    dinv_k<<<(n + TB - 1) / TB, TB>>>(n);
    blocksum_k<<<nb, SCAN_B>>>(n);
    scanblocks_k<<<1, 128>>>(nb);
    scanfinal_k<<<nb, SCAN_B>>>(n);
    scatter_k<<<(E + TB - 1) / TB, TB>>>(src, dst, E);

    int aggBlocks = (int)(((long long)n * 32 + TB - 1) / TB);
    agg1_k<<<aggBlocks, TB>>>(x, n);
    gemm1_mma<<<gblk, TB, SM1>>>(b1, n);
    gemm2_mma<<<gblk, TB, SM2>>>(n);
    agg2_k<<<aggBlocks, TB>>>(b2, out, n);
}

// round 7
// speedup vs baseline: 2.0076x; 1.0337x over previous
#include <cuda_runtime.h>
#include <cuda_fp16.h>
#include <cstdint>

#define NMAX 100000
#define EMAX 1600000
#define IND 128
#define HID 128
#define OUTD 64
#define SCAN_B 1024
#define MAXBLK 128

// ---------------- scratch (static __device__, allocation-free) ----------------
__device__ int   g_degc[NMAX];
__device__ float g_dinv[NMAX];
__device__ int   g_rowptr[NMAX + 1];
__device__ int   g_pos[NMAX];
__device__ int   g_csr_src[EMAX];
__device__ int   g_blocksum[MAXBLK];
__device__ int   g_blockoff[MAXBLK];
__device__ float g_aggx[(size_t)NMAX * IND];
__device__ float g_h[(size_t)NMAX * HID];
__device__ float g_h2[(size_t)NMAX * OUTD];
__device__ __half g_x16[(size_t)NMAX * IND];    // x * dinv, f16 (gather table L1)
__device__ __half g_h216[(size_t)NMAX * OUTD];  // h2 * dinv, f16 (gather table L2)
// W pre-transposed to [n][k] f16 hi/lo (hi + lo == fp32 weight to ~2^-22)
__device__ __half g_w1hi[HID * IND];
__device__ __half g_w1lo[HID * IND];
__device__ __half g_w2hi[OUTD * IND];
__device__ __half g_w2lo[OUTD * IND];

__device__ __forceinline__ uint32_t smem_u32(const void* p) {
    uint32_t a;
    asm("{ .reg .u64 t; cvta.to.shared.u64 t, %1; cvt.u32.u64 %0, t; }" : "=r"(a) : "l"(p));
    return a;
}
__device__ __forceinline__ void ldm_x4(uint32_t* r, uint32_t addr) {
    asm volatile("ldmatrix.sync.aligned.m8n8.x4.shared.b16 {%0,%1,%2,%3}, [%4];"
                 : "=r"(r[0]), "=r"(r[1]), "=r"(r[2]), "=r"(r[3]) : "r"(addr));
}
__device__ __forceinline__ void mma16816(float* d, const uint32_t* a, const uint32_t* b) {
    asm volatile(
        "mma.sync.aligned.m16n8k16.row.col.f32.f16.f16.f32 "
        "{%0,%1,%2,%3}, {%4,%5,%6,%7}, {%8,%9}, {%0,%1,%2,%3};"
        : "+f"(d[0]), "+f"(d[1]), "+f"(d[2]), "+f"(d[3])
        : "r"(a[0]), "r"(a[1]), "r"(a[2]), "r"(a[3]), "r"(b[0]), "r"(b[1]));
}
__device__ __forceinline__ void split_h(float v, __half& hi, __half& lo) {
    hi = __float2half_rn(v);
    lo = __float2half_rn(v - __half2float(hi));
}

// ---------------- CSR build ----------------
__global__ void deg4_k(const int* __restrict__ dst, int E4, int E) {
    int i = blockIdx.x * blockDim.x + threadIdx.x;
    if (i < E4) {
        int4 d = ((const int4*)dst)[i];
        atomicAdd(&g_degc[d.x], 1);
        atomicAdd(&g_degc[d.y], 1);
        atomicAdd(&g_degc[d.z], 1);
        atomicAdd(&g_degc[d.w], 1);
    }
    if (i == 0)
        for (int k = E4 * 4; k < E; k++) atomicAdd(&g_degc[dst[k]], 1);
}
__global__ void deg_k(const int* __restrict__ dst, int E) {
    int i = blockIdx.x * blockDim.x + threadIdx.x;
    if (i < E) atomicAdd(&g_degc[dst[i]], 1);
}
// blocksum + dinv fused
__global__ void blocksum_k(int n) {
    __shared__ int red[32];
    int i = blockIdx.x * SCAN_B + threadIdx.x;
    int v = (i < n) ? g_degc[i] : 0;
    if (i < n) g_dinv[i] = rsqrtf((float)v + 1.0f);
    int lane = threadIdx.x & 31, w = threadIdx.x >> 5;
    int s = v;
#pragma unroll
    for (int o = 16; o > 0; o >>= 1) s += __shfl_down_sync(0xffffffffu, s, o);
    if (lane == 0) red[w] = s;
    __syncthreads();
    if (w == 0) {
        int t = red[lane];
#pragma unroll
        for (int o = 16; o > 0; o >>= 1) t += __shfl_down_sync(0xffffffffu, t, o);
        if (lane == 0) g_blocksum[blockIdx.x] = t;
    }
}
__global__ void scanblocks_k(int nb) {
    __shared__ int ws[4];
    int t = threadIdx.x;
    int lane = t & 31, w = t >> 5;
    int v = (t < nb) ? g_blocksum[t] : 0;
    int x = v;
#pragma unroll
    for (int o = 1; o < 32; o <<= 1) {
        int y = __shfl_up_sync(0xffffffffu, x, o);
        if (lane >= o) x += y;
    }
    if (lane == 31) ws[w] = x;
    __syncthreads();
    if (w == 0 && lane < 4) {
        int s = ws[lane];
#pragma unroll
        for (int o = 1; o < 4; o <<= 1) {
            int y = __shfl_up_sync(0x0000000fu, s, o);
            if (lane >= o) s += y;
        }
        ws[lane] = s;
    }
    __syncthreads();
    int incl = x + (w > 0 ? ws[w - 1] : 0);
    if (t < nb) g_blockoff[t] = incl - v;
}
__global__ void scanfinal_k(int n) {
    __shared__ int wsum[32];
    int b = blockIdx.x, t = threadIdx.x;
    int i = b * SCAN_B + t;
    int v = (i < n) ? g_degc[i] : 0;
    int lane = t & 31, w = t >> 5;
    int x = v;
#pragma unroll
    for (int o = 1; o < 32; o <<= 1) {
        int y = __shfl_up_sync(0xffffffffu, x, o);
        if (lane >= o) x += y;
    }
    if (lane == 31) wsum[w] = x;
    __syncthreads();
    if (w == 0) {
        int s = wsum[lane];
#pragma unroll
        for (int o = 1; o < 32; o <<= 1) {
            int y = __shfl_up_sync(0xffffffffu, s, o);
            if (lane >= o) s += y;
        }
        wsum[lane] = s;
    }
    __syncthreads();
    int incl = x + (w > 0 ? wsum[w - 1] : 0);
    int excl = incl - v + g_blockoff[b];
    if (i < n) {
        g_rowptr[i] = excl;
        g_pos[i] = excl;
        if (i == n - 1) g_rowptr[n] = excl + v;
    }
}
__global__ void scatter4_k(const int* __restrict__ src, const int* __restrict__ dst,
                           int E4, int E) {
    int i = blockIdx.x * blockDim.x + threadIdx.x;
    if (i < E4) {
        int4 s = ((const int4*)src)[i];
        int4 d = ((const int4*)dst)[i];
        g_csr_src[atomicAdd(&g_pos[d.x], 1)] = s.x;
        g_csr_src[atomicAdd(&g_pos[d.y], 1)] = s.y;
        g_csr_src[atomicAdd(&g_pos[d.z], 1)] = s.z;
        g_csr_src[atomicAdd(&g_pos[d.w], 1)] = s.w;
    }
    if (i == 0)
        for (int k = E4 * 4; k < E; k++)
            g_csr_src[atomicAdd(&g_pos[dst[k]], 1)] = src[k];
}
__global__ void scatter_k(const int* __restrict__ src, const int* __restrict__ dst, int E) {
    int e = blockIdx.x * blockDim.x + threadIdx.x;
    if (e < E) g_csr_src[atomicAdd(&g_pos[dst[e]], 1)] = src[e];
}

// ---------------- x16 = half(x * dinv) ----------------
__global__ void x16conv_k(const float* __restrict__ x, int n) {
    int i = blockIdx.x * blockDim.x + threadIdx.x;  // n*16 threads, 8 floats each
    if (i >= n * 16) return;
    int row = i >> 4, seg = i & 15;
    float dv = g_dinv[row];
    const float4* xp = (const float4*)(x + (size_t)row * IND + seg * 8);
    float4 a = xp[0], b = xp[1];
    __half2 h0 = __floats2half2_rn(a.x * dv, a.y * dv);
    __half2 h1 = __floats2half2_rn(a.z * dv, a.w * dv);
    __half2 h2 = __floats2half2_rn(b.x * dv, b.y * dv);
    __half2 h3 = __floats2half2_rn(b.z * dv, b.w * dv);
    uint4 o;
    o.x = *(uint32_t*)&h0; o.y = *(uint32_t*)&h1;
    o.z = *(uint32_t*)&h2; o.w = *(uint32_t*)&h3;
    *(uint4*)(g_x16 + (size_t)row * IND + seg * 8) = o;
}

// ---------------- aggregation (CSR, warp per dst, fp16 gather) ----------------
// aggx[i] = x[i]*dinv[i]^2 + dinv[i] * sum_j x16[src_j]        (x16 pre-scaled by dinv[src])
__global__ void agg1_k(const float* __restrict__ x, int n) {
    int w = (blockIdx.x * blockDim.x + threadIdx.x) >> 5;
    if (w >= n) return;
    int c = threadIdx.x & 31;
    float di = g_dinv[w];
    float d2 = di * di;
    float4 self = ((const float4*)(x + (size_t)w * IND))[c];
    float4 sum = make_float4(0.f, 0.f, 0.f, 0.f);
    int j = g_rowptr[w], end = g_rowptr[w + 1];
    for (; j + 1 < end; j += 2) {
        int s0 = __ldg(&g_csr_src[j]);
        int s1 = __ldg(&g_csr_src[j + 1]);
        uint2 p0 = __ldg((const uint2*)(g_x16 + (size_t)s0 * IND) + c);
        uint2 p1 = __ldg((const uint2*)(g_x16 + (size_t)s1 * IND) + c);
        float2 a0 = __half22float2(*(__half2*)&p0.x);
        float2 b0 = __half22float2(*(__half2*)&p0.y);
        float2 a1 = __half22float2(*(__half2*)&p1.x);
        float2 b1 = __half22float2(*(__half2*)&p1.y);
        sum.x += a0.x + a1.x; sum.y += a0.y + a1.y;
        sum.z += b0.x + b1.x; sum.w += b0.y + b1.y;
    }
    if (j < end) {
        int s = __ldg(&g_csr_src[j]);
        uint2 p = __ldg((const uint2*)(g_x16 + (size_t)s * IND) + c);
        float2 a = __half22float2(*(__half2*)&p.x);
        float2 b = __half22float2(*(__half2*)&p.y);
        sum.x += a.x; sum.y += a.y; sum.z += b.x; sum.w += b.y;
    }
    float4 o;
    o.x = self.x * d2 + sum.x * di;
    o.y = self.y * d2 + sum.y * di;
    o.z = self.z * d2 + sum.z * di;
    o.w = self.w * d2 + sum.w * di;
    ((float4*)(g_aggx + (size_t)w * IND))[c] = o;
}

// out[i] = h2[i]*dinv[i]^2 + b2 + dinv[i] * sum_j h216[src_j]
__global__ void agg2_k(const float* __restrict__ b2, float* __restrict__ out, int n) {
    int w = (blockIdx.x * blockDim.x + threadIdx.x) >> 5;
    if (w >= n) return;
    int c = threadIdx.x & 31;
    float di = g_dinv[w];
    float d2 = di * di;
    float2 bb = ((const float2*)b2)[c];
    float2 self = ((const float2*)(g_h2 + (size_t)w * OUTD))[c];
    float2 sum = make_float2(0.f, 0.f);
    int j = g_rowptr[w], end = g_rowptr[w + 1];
    for (; j + 1 < end; j += 2) {
        int s0 = __ldg(&g_csr_src[j]);
        int s1 = __ldg(&g_csr_src[j + 1]);
        uint32_t p0 = __ldg((const uint32_t*)(g_h216 + (size_t)s0 * OUTD) + c);
        uint32_t p1 = __ldg((const uint32_t*)(g_h216 + (size_t)s1 * OUTD) + c);
        float2 a0 = __half22float2(*(__half2*)&p0);
        float2 a1 = __half22float2(*(__half2*)&p1);
        sum.x += a0.x + a1.x; sum.y += a0.y + a1.y;
    }
    if (j < end) {
        int s = __ldg(&g_csr_src[j]);
        uint32_t p = __ldg((const uint32_t*)(g_h216 + (size_t)s * OUTD) + c);
        float2 a = __half22float2(*(__half2*)&p);
        sum.x += a.x; sum.y += a.y;
    }
    float2 o;
    o.x = self.x * d2 + bb.x + sum.x * di;
    o.y = self.y * d2 + bb.y + sum.y * di;
    ((float2*)(out + (size_t)w * OUTD))[c] = o;
}

// ---------------- W prep ----------------
__global__ void w1prep_k(const float* __restrict__ W1) {
    int i = blockIdx.x * blockDim.x + threadIdx.x;
    if (i >= HID * IND) return;
    int nn = i & 127, k = i >> 7;
    float w = W1[k * HID + nn];
    __half hi, lo; split_h(w, hi, lo);
    g_w1hi[nn * IND + k] = hi;
    g_w1lo[nn * IND + k] = lo;
}
__global__ void w2prep_k(const float* __restrict__ W2) {
    int i = blockIdx.x * blockDim.x + threadIdx.x;
    if (i >= OUTD * IND) return;
    int nn = i & 63, k = i >> 6;
    float w = W2[k * OUTD + nn];
    __half hi, lo; split_h(w, hi, lo);
    g_w2hi[nn * IND + k] = hi;
    g_w2lo[nn * IND + k] = lo;
}

// ---------------- HMMA GEMMs ----------------
#define LDA 136

__global__ __launch_bounds__(256, 1) void gemm1_mma(const float* __restrict__ b1, int n) {
    extern __shared__ __half sm[];
    __half* Ah = sm;
    __half* Al = Ah + 128 * LDA;
    __half* Bh = Al + 128 * LDA;
    __half* Bl = Bh + 128 * LDA;
    int tid = threadIdx.x, wid = tid >> 5, lane = tid & 31;
    int r0 = blockIdx.x * 128;

    for (int i = tid; i < 4096; i += 256) {
        int row = i >> 5, c = i & 31;
        int gr = r0 + row;
        float4 v = (gr < n) ? ((const float4*)(g_aggx + (size_t)gr * IND))[c]
                            : make_float4(0.f, 0.f, 0.f, 0.f);
        __half h0, h1, h2, h3, l0, l1, l2, l3;
        split_h(v.x, h0, l0); split_h(v.y, h1, l1);
        split_h(v.z, h2, l2); split_h(v.w, h3, l3);
        int o = row * LDA + c * 4;
        *(__half2*)(Ah + o) = __halves2half2(h0, h1);
        *(__half2*)(Ah + o + 2) = __halves2half2(h2, h3);
        *(__half2*)(Al + o) = __halves2half2(l0, l1);
        *(__half2*)(Al + o + 2) = __halves2half2(l2, l3);
    }
    for (int i = tid; i < 2048; i += 256) {
        int row = i >> 4, seg = i & 15;
        *(uint4*)(Bh + row * LDA + seg * 8) = ((const uint4*)g_w1hi)[i];
        *(uint4*)(Bl + row * LDA + seg * 8) = ((const uint4*)g_w1lo)[i];
    }
    __syncthreads();

    uint32_t ah_b = smem_u32(Ah), al_b = smem_u32(Al);
    uint32_t bh_b = smem_u32(Bh), bl_b = smem_u32(Bl);
    int a_row = wid * 16 + (lane & 15);
    int a_co = (lane >> 4) * 8;
    uint32_t a_off = (uint32_t)(a_row * LDA + a_co) * 2;
    int b_row = (lane & 7) + ((lane >> 4) << 3);
    int b_co = ((lane >> 3) & 1) * 8;
    uint32_t b_off = (uint32_t)(b_row * LDA + b_co) * 2;

    float acc[16][4];
#pragma unroll
    for (int t = 0; t < 16; t++)
#pragma unroll
        for (int j = 0; j < 4; j++) acc[t][j] = 0.f;

#pragma unroll
    for (int ks = 0; ks < 8; ks++) {
        uint32_t ahr[4], alr[4];
        ldm_x4(ahr, ah_b + a_off + ks * 32);
        ldm_x4(alr, al_b + a_off + ks * 32);
#pragma unroll
        for (int np = 0; np < 8; np++) {
            uint32_t bhr[4], blr[4];
            uint32_t bo = b_off + (uint32_t)(np * 16 * LDA * 2) + ks * 32;
            ldm_x4(bhr, bh_b + bo);
            ldm_x4(blr, bl_b + bo);
            mma16816(acc[2 * np], ahr, bhr);
            mma16816(acc[2 * np], ahr, blr);
            mma16816(acc[2 * np], alr, bhr);
            mma16816(acc[2 * np + 1], ahr, bhr + 2);
            mma16816(acc[2 * np + 1], ahr, blr + 2);
            mma16816(acc[2 * np + 1], alr, bhr + 2);
        }
    }

    int grp = lane >> 2, qid = lane & 3;
    int rowA = r0 + wid * 16 + grp;
    int rowB = rowA + 8;
#pragma unroll
    for (int t = 0; t < 16; t++) {
        int col = t * 8 + qid * 2;
        float2 bb = *(const float2*)(b1 + col);
        if (rowA < n) {
            float2 o = make_float2(fmaxf(acc[t][0] + bb.x, 0.f),
                                   fmaxf(acc[t][1] + bb.y, 0.f));
            *(float2*)(g_h + (size_t)rowA * HID + col) = o;
        }
        if (rowB < n) {
            float2 o = make_float2(fmaxf(acc[t][2] + bb.x, 0.f),
                                   fmaxf(acc[t][3] + bb.y, 0.f));
            *(float2*)(g_h + (size_t)rowB * HID + col) = o;
        }
    }
}

// GEMM2: h2 = h @ W2 (fp32) and h216 = h2 * dinv (f16 gather table)
__global__ __launch_bounds__(256, 1) void gemm2_mma(int n) {
    extern __shared__ __half sm[];
    __half* Ah = sm;
    __half* Al = Ah + 128 * LDA;
    __half* Bh = Al + 128 * LDA;
    __half* Bl = Bh + 64 * LDA;
    int tid = threadIdx.x, wid = tid >> 5, lane = tid & 31;
    int r0 = blockIdx.x * 128;

    for (int i = tid; i < 4096; i += 256) {
        int row = i >> 5, c = i & 31;
        int gr = r0 + row;
        float4 v = (gr < n) ? ((const float4*)(g_h + (size_t)gr * HID))[c]
                            : make_float4(0.f, 0.f, 0.f, 0.f);
        __half h0, h1, h2, h3, l0, l1, l2, l3;
        split_h(v.x, h0, l0); split_h(v.y, h1, l1);
        split_h(v.z, h2, l2); split_h(v.w, h3, l3);
        int o = row * LDA + c * 4;
        *(__half2*)(Ah + o) = __halves2half2(h0, h1);
        *(__half2*)(Ah + o + 2) = __halves2half2(h2, h3);
        *(__half2*)(Al + o) = __halves2half2(l0, l1);
        *(__half2*)(Al + o + 2) = __halves2half2(l2, l3);
    }
    for (int i = tid; i < 1024; i += 256) {
        int row = i >> 4, seg = i & 15;
        *(uint4*)(Bh + row * LDA + seg * 8) = ((const uint4*)g_w2hi)[i];
        *(uint4*)(Bl + row * LDA + seg * 8) = ((const uint4*)g_w2lo)[i];
    }
    __syncthreads();

    uint32_t ah_b = smem_u32(Ah), al_b = smem_u32(Al);
    uint32_t bh_b = smem_u32(Bh), bl_b = smem_u32(Bl);
    int a_row = wid * 16 + (lane & 15);
    int a_co = (lane >> 4) * 8;
    uint32_t a_off = (uint32_t)(a_row * LDA + a_co) * 2;
    int b_row = (lane & 7) + ((lane >> 4) << 3);
    int b_co = ((lane >> 3) & 1) * 8;
    uint32_t b_off = (uint32_t)(b_row * LDA + b_co) * 2;

    float acc[8][4];
#pragma unroll
    for (int t = 0; t < 8; t++)
#pragma unroll
        for (int j = 0; j < 4; j++) acc[t][j] = 0.f;

#pragma unroll
    for (int ks = 0; ks < 8; ks++) {
        uint32_t ahr[4], alr[4];
        ldm_x4(ahr, ah_b + a_off + ks * 32);
        ldm_x4(alr, al_b + a_off + ks * 32);
#pragma unroll
        for (int np = 0; np < 4; np++) {
            uint32_t bhr[4], blr[4];
            uint32_t bo = b_off + (uint32_t)(np * 16 * LDA * 2) + ks * 32;
            ldm_x4(bhr, bh_b + bo);
            ldm_x4(blr, bl_b + bo);
            mma16816(acc[2 * np], ahr, bhr);
            mma16816(acc[2 * np], ahr, blr);
            mma16816(acc[2 * np], alr, bhr);
            mma16816(acc[2 * np + 1], ahr, bhr + 2);
            mma16816(acc[2 * np + 1], ahr, blr + 2);
            mma16816(acc[2 * np + 1], alr, bhr + 2);
        }
    }

    int grp = lane >> 2, qid = lane & 3;
    int rowA = r0 + wid * 16 + grp;
    int rowB = rowA + 8;
    float dva = (rowA < n) ? g_dinv[rowA] : 0.f;
    float dvb = (rowB < n) ? g_dinv[rowB] : 0.f;
#pragma unroll
    for (int t = 0; t < 8; t++) {
        int col = t * 8 + qid * 2;
        if (rowA < n) {
            *(float2*)(g_h2 + (size_t)rowA * OUTD + col) = make_float2(acc[t][0], acc[t][1]);
            *(__half2*)(g_h216 + (size_t)rowA * OUTD + col) =
                __floats2half2_rn(acc[t][0] * dva, acc[t][1] * dva);
        }
        if (rowB < n) {
            *(float2*)(g_h2 + (size_t)rowB * OUTD + col) = make_float2(acc[t][2], acc[t][3]);
            *(__half2*)(g_h216 + (size_t)rowB * OUTD + col) =
                __floats2half2_rn(acc[t][2] * dvb, acc[t][3] * dvb);
        }
    }
}

// ---------------- launch ----------------
extern "C" void kernel_launch(void* const* d_in, const int* in_sizes, int n_in,
                              void* d_out, int out_size) {
    const float* x  = (const float*)d_in[0];
    const int*   ei = (const int*)d_in[1];
    const float* W1 = (const float*)d_in[2];
    const float* b1 = (const float*)d_in[3];
    const float* W2 = (const float*)d_in[4];
    const float* b2 = (const float*)d_in[5];
    float* out      = (float*)d_out;

    int n = in_sizes[0] / IND;
    int E = in_sizes[1] / 2;
    const int* src = ei;
    const int* dst = ei + E;

    const int SM1 = (128 * LDA * 2 + 128 * LDA * 2) * 2;
    const int SM2 = (128 * LDA * 2) * 2 + (64 * LDA * 2) * 2;
    cudaFuncSetAttribute(gemm1_mma, cudaFuncAttributeMaxDynamicSharedMemorySize, SM1);
    cudaFuncSetAttribute(gemm2_mma, cudaFuncAttributeMaxDynamicSharedMemorySize, SM2);

    const int TB = 256;
    int nb = (n + SCAN_B - 1) / SCAN_B;
    int gblk = (n + 127) / 128;
    bool vec4 = (E % 4 == 0) && ((((uintptr_t)dst) & 15) == 0) && ((((uintptr_t)src) & 15) == 0);

    w1prep_k<<<(HID * IND + TB - 1) / TB, TB>>>(W1);
    w2prep_k<<<(OUTD * IND + TB - 1) / TB, TB>>>(W2);

    void* degp = nullptr;
    cudaGetSymbolAddress(&degp, g_degc);
    cudaMemsetAsync(degp, 0, (size_t)n * sizeof(int));

    if (vec4) deg4_k<<<(E / 4 + TB - 1) / TB, TB>>>(dst, E / 4, E);
    else      deg_k<<<(E + TB - 1) / TB, TB>>>(dst, E);
    blocksum_k<<<nb, SCAN_B>>>(n);
    scanblocks_k<<<1, 128>>>(nb);
    scanfinal_k<<<nb, SCAN_B>>>(n);
    if (vec4) scatter4_k<<<(E / 4 + TB - 1) / TB, TB>>>(src, dst, E / 4, E);
    else      scatter_k<<<(E + TB - 1) / TB, TB>>>(src, dst, E);

    x16conv_k<<<(n * 16 + TB - 1) / TB, TB>>>(x, n);

    int aggBlocks = (int)(((long long)n * 32 + TB - 1) / TB);
    agg1_k<<<aggBlocks, TB>>>(x, n);
    gemm1_mma<<<gblk, TB, SM1>>>(b1, n);
    gemm2_mma<<<gblk, TB, SM2>>>(n);
    agg2_k<<<aggBlocks, TB>>>(b2, out, n);
}

// round 8
// speedup vs baseline: 2.1339x; 1.0629x over previous
#include <cuda_runtime.h>
#include <cuda_fp16.h>
#include <cstdint>

#define NMAX 100000
#define EMAX 1600000
#define IND 128
#define HID 128
#define OUTD 64
#define SCAN_B 1024
#define MAXBLK 128

// ---------------- scratch (static __device__, allocation-free) ----------------
__device__ int   g_degc[NMAX];
__device__ float g_dinv[NMAX];
__device__ int   g_rowptr[NMAX + 1];
__device__ int   g_pos[NMAX];
__device__ int   g_csr_src[EMAX];
__device__ int   g_blocksum[MAXBLK];
__device__ int   g_blockoff[MAXBLK];
__device__ float g_aggx[(size_t)NMAX * IND];
__device__ float g_h[(size_t)NMAX * HID];
__device__ __half g_x16[(size_t)NMAX * IND];    // x * dinv, f16 (gather table L1)
__device__ __half g_h216[(size_t)NMAX * OUTD];  // h2 * dinv, f16 (gather table L2)
// W pre-transposed to [n][k] f16 hi/lo (hi + lo == fp32 weight to ~2^-22)
__device__ __half g_w1hi[HID * IND];
__device__ __half g_w1lo[HID * IND];
__device__ __half g_w2hi[OUTD * IND];
__device__ __half g_w2lo[OUTD * IND];

__device__ __forceinline__ uint32_t smem_u32(const void* p) {
    uint32_t a;
    asm("{ .reg .u64 t; cvta.to.shared.u64 t, %1; cvt.u32.u64 %0, t; }" : "=r"(a) : "l"(p));
    return a;
}
__device__ __forceinline__ void ldm_x4(uint32_t* r, uint32_t addr) {
    asm volatile("ldmatrix.sync.aligned.m8n8.x4.shared.b16 {%0,%1,%2,%3}, [%4];"
                 : "=r"(r[0]), "=r"(r[1]), "=r"(r[2]), "=r"(r[3]) : "r"(addr));
}
__device__ __forceinline__ void mma16816(float* d, const uint32_t* a, const uint32_t* b) {
    asm volatile(
        "mma.sync.aligned.m16n8k16.row.col.f32.f16.f16.f32 "
        "{%0,%1,%2,%3}, {%4,%5,%6,%7}, {%8,%9}, {%0,%1,%2,%3};"
        : "+f"(d[0]), "+f"(d[1]), "+f"(d[2]), "+f"(d[3])
        : "r"(a[0]), "r"(a[1]), "r"(a[2]), "r"(a[3]), "r"(b[0]), "r"(b[1]));
}
__device__ __forceinline__ void split_h(float v, __half& hi, __half& lo) {
    hi = __float2half_rn(v);
    lo = __float2half_rn(v - __half2float(hi));
}

// ---------------- CSR build ----------------
__global__ void deg4_k(const int* __restrict__ dst, int E4, int E) {
    int i = blockIdx.x * blockDim.x + threadIdx.x;
    if (i < E4) {
        int4 d = ((const int4*)dst)[i];
        atomicAdd(&g_degc[d.x], 1);
        atomicAdd(&g_degc[d.y], 1);
        atomicAdd(&g_degc[d.z], 1);
        atomicAdd(&g_degc[d.w], 1);
    }
    if (i == 0)
        for (int k = E4 * 4; k < E; k++) atomicAdd(&g_degc[dst[k]], 1);
}
__global__ void deg_k(const int* __restrict__ dst, int E) {
    int i = blockIdx.x * blockDim.x + threadIdx.x;
    if (i < E) atomicAdd(&g_degc[dst[i]], 1);
}
// blocksum + dinv fused
__global__ void blocksum_k(int n) {
    __shared__ int red[32];
    int i = blockIdx.x * SCAN_B + threadIdx.x;
    int v = (i < n) ? g_degc[i] : 0;
    if (i < n) g_dinv[i] = rsqrtf((float)v + 1.0f);
    int lane = threadIdx.x & 31, w = threadIdx.x >> 5;
    int s = v;
#pragma unroll
    for (int o = 16; o > 0; o >>= 1) s += __shfl_down_sync(0xffffffffu, s, o);
    if (lane == 0) red[w] = s;
    __syncthreads();
    if (w == 0) {
        int t = red[lane];
#pragma unroll
        for (int o = 16; o > 0; o >>= 1) t += __shfl_down_sync(0xffffffffu, t, o);
        if (lane == 0) g_blocksum[blockIdx.x] = t;
    }
}
__global__ void scanblocks_k(int nb) {
    __shared__ int ws[4];
    int t = threadIdx.x;
    int lane = t & 31, w = t >> 5;
    int v = (t < nb) ? g_blocksum[t] : 0;
    int x = v;
#pragma unroll
    for (int o = 1; o < 32; o <<= 1) {
        int y = __shfl_up_sync(0xffffffffu, x, o);
        if (lane >= o) x += y;
    }
    if (lane == 31) ws[w] = x;
    __syncthreads();
    if (w == 0 && lane < 4) {
        int s = ws[lane];
#pragma unroll
        for (int o = 1; o < 4; o <<= 1) {
            int y = __shfl_up_sync(0x0000000fu, s, o);
            if (lane >= o) s += y;
        }
        ws[lane] = s;
    }
    __syncthreads();
    int incl = x + (w > 0 ? ws[w - 1] : 0);
    if (t < nb) g_blockoff[t] = incl - v;
}
__global__ void scanfinal_k(int n) {
    __shared__ int wsum[32];
    int b = blockIdx.x, t = threadIdx.x;
    int i = b * SCAN_B + t;
    int v = (i < n) ? g_degc[i] : 0;
    int lane = t & 31, w = t >> 5;
    int x = v;
#pragma unroll
    for (int o = 1; o < 32; o <<= 1) {
        int y = __shfl_up_sync(0xffffffffu, x, o);
        if (lane >= o) x += y;
    }
    if (lane == 31) wsum[w] = x;
    __syncthreads();
    if (w == 0) {
        int s = wsum[lane];
#pragma unroll
        for (int o = 1; o < 32; o <<= 1) {
            int y = __shfl_up_sync(0xffffffffu, s, o);
            if (lane >= o) s += y;
        }
        wsum[lane] = s;
    }
    __syncthreads();
    int incl = x + (w > 0 ? wsum[w - 1] : 0);
    int excl = incl - v + g_blockoff[b];
    if (i < n) {
        g_rowptr[i] = excl;
        g_pos[i] = excl;
        if (i == n - 1) g_rowptr[n] = excl + v;
    }
}
__global__ void scatter4_k(const int* __restrict__ src, const int* __restrict__ dst,
                           int E4, int E) {
    int i = blockIdx.x * blockDim.x + threadIdx.x;
    if (i < E4) {
        int4 s = ((const int4*)src)[i];
        int4 d = ((const int4*)dst)[i];
        g_csr_src[atomicAdd(&g_pos[d.x], 1)] = s.x;
        g_csr_src[atomicAdd(&g_pos[d.y], 1)] = s.y;
        g_csr_src[atomicAdd(&g_pos[d.z], 1)] = s.z;
        g_csr_src[atomicAdd(&g_pos[d.w], 1)] = s.w;
    }
    if (i == 0)
        for (int k = E4 * 4; k < E; k++)
            g_csr_src[atomicAdd(&g_pos[dst[k]], 1)] = src[k];
}
__global__ void scatter_k(const int* __restrict__ src, const int* __restrict__ dst, int E) {
    int e = blockIdx.x * blockDim.x + threadIdx.x;
    if (e < E) g_csr_src[atomicAdd(&g_pos[dst[e]], 1)] = src[e];
}

// ---------------- x16 = half(x * dinv) ----------------
__global__ void x16conv_k(const float* __restrict__ x, int n) {
    int i = blockIdx.x * blockDim.x + threadIdx.x;  // n*16 threads, 8 floats each
    if (i >= n * 16) return;
    int row = i >> 4, seg = i & 15;
    float dv = g_dinv[row];
    const float4* xp = (const float4*)(x + (size_t)row * IND + seg * 8);
    float4 a = xp[0], b = xp[1];
    __half2 h0 = __floats2half2_rn(a.x * dv, a.y * dv);
    __half2 h1 = __floats2half2_rn(a.z * dv, a.w * dv);
    __half2 h2 = __floats2half2_rn(b.x * dv, b.y * dv);
    __half2 h3 = __floats2half2_rn(b.z * dv, b.w * dv);
    uint4 o;
    o.x = *(uint32_t*)&h0; o.y = *(uint32_t*)&h1;
    o.z = *(uint32_t*)&h2; o.w = *(uint32_t*)&h3;
    *(uint4*)(g_x16 + (size_t)row * IND + seg * 8) = o;
}

// ---------------- aggregation (CSR, warp per dst, fp16 gather, 4-way MLP) ----------------
__device__ __forceinline__ void acc_x16(float4& sum, uint2 p) {
    float2 a = __half22float2(*(__half2*)&p.x);
    float2 b = __half22float2(*(__half2*)&p.y);
    sum.x += a.x; sum.y += a.y; sum.z += b.x; sum.w += b.y;
}

// aggx[i] = di * (x16[i] + sum_j x16[src_j])     (x16 pre-scaled by dinv)
__global__ void agg1_k(int n) {
    int w = (blockIdx.x * blockDim.x + threadIdx.x) >> 5;
    if (w >= n) return;
    int c = threadIdx.x & 31;
    float di = g_dinv[w];
    float4 sum = make_float4(0.f, 0.f, 0.f, 0.f);
    acc_x16(sum, __ldg((const uint2*)(g_x16 + (size_t)w * IND) + c));  // self
    int j = g_rowptr[w], end = g_rowptr[w + 1];
    for (; j + 3 < end; j += 4) {
        int s0 = __ldg(&g_csr_src[j]);
        int s1 = __ldg(&g_csr_src[j + 1]);
        int s2 = __ldg(&g_csr_src[j + 2]);
        int s3 = __ldg(&g_csr_src[j + 3]);
        uint2 p0 = __ldg((const uint2*)(g_x16 + (size_t)s0 * IND) + c);
        uint2 p1 = __ldg((const uint2*)(g_x16 + (size_t)s1 * IND) + c);
        uint2 p2 = __ldg((const uint2*)(g_x16 + (size_t)s2 * IND) + c);
        uint2 p3 = __ldg((const uint2*)(g_x16 + (size_t)s3 * IND) + c);
        acc_x16(sum, p0); acc_x16(sum, p1); acc_x16(sum, p2); acc_x16(sum, p3);
    }
    for (; j < end; j++) {
        int s = __ldg(&g_csr_src[j]);
        acc_x16(sum, __ldg((const uint2*)(g_x16 + (size_t)s * IND) + c));
    }
    float4 o;
    o.x = sum.x * di; o.y = sum.y * di; o.z = sum.z * di; o.w = sum.w * di;
    ((float4*)(g_aggx + (size_t)w * IND))[c] = o;
}

// out[i] = di * (h216[i] + sum_j h216[src_j]) + b2
__global__ void agg2_k(const float* __restrict__ b2, float* __restrict__ out, int n) {
    int w = (blockIdx.x * blockDim.x + threadIdx.x) >> 5;
    if (w >= n) return;
    int c = threadIdx.x & 31;
    float di = g_dinv[w];
    float2 bb = ((const float2*)b2)[c];
    float2 sum;
    {
        uint32_t p = __ldg((const uint32_t*)(g_h216 + (size_t)w * OUTD) + c);  // self
        sum = __half22float2(*(__half2*)&p);
    }
    int j = g_rowptr[w], end = g_rowptr[w + 1];
    for (; j + 3 < end; j += 4) {
        int s0 = __ldg(&g_csr_src[j]);
        int s1 = __ldg(&g_csr_src[j + 1]);
        int s2 = __ldg(&g_csr_src[j + 2]);
        int s3 = __ldg(&g_csr_src[j + 3]);
        uint32_t p0 = __ldg((const uint32_t*)(g_h216 + (size_t)s0 * OUTD) + c);
        uint32_t p1 = __ldg((const uint32_t*)(g_h216 + (size_t)s1 * OUTD) + c);
        uint32_t p2 = __ldg((const uint32_t*)(g_h216 + (size_t)s2 * OUTD) + c);
        uint32_t p3 = __ldg((const uint32_t*)(g_h216 + (size_t)s3 * OUTD) + c);
        float2 a0 = __half22float2(*(__half2*)&p0);
        float2 a1 = __half22float2(*(__half2*)&p1);
        float2 a2 = __half22float2(*(__half2*)&p2);
        float2 a3 = __half22float2(*(__half2*)&p3);
        sum.x += (a0.x + a1.x) + (a2.x + a3.x);
        sum.y += (a0.y + a1.y) + (a2.y + a3.y);
    }
    for (; j < end; j++) {
        int s = __ldg(&g_csr_src[j]);
        uint32_t p = __ldg((const uint32_t*)(g_h216 + (size_t)s * OUTD) + c);
        float2 a = __half22float2(*(__half2*)&p);
        sum.x += a.x; sum.y += a.y;
    }
    float2 o;
    o.x = sum.x * di + bb.x;
    o.y = sum.y * di + bb.y;
    ((float2*)(out + (size_t)w * OUTD))[c] = o;
}

// ---------------- W prep ----------------
__global__ void w1prep_k(const float* __restrict__ W1) {
    int i = blockIdx.x * blockDim.x + threadIdx.x;
    if (i >= HID * IND) return;
    int nn = i & 127, k = i >> 7;
    float w = W1[k * HID + nn];
    __half hi, lo; split_h(w, hi, lo);
    g_w1hi[nn * IND + k] = hi;
    g_w1lo[nn * IND + k] = lo;
}
__global__ void w2prep_k(const float* __restrict__ W2) {
    int i = blockIdx.x * blockDim.x + threadIdx.x;
    if (i >= OUTD * IND) return;
    int nn = i & 63, k = i >> 6;
    float w = W2[k * OUTD + nn];
    __half hi, lo; split_h(w, hi, lo);
    g_w2hi[nn * IND + k] = hi;
    g_w2lo[nn * IND + k] = lo;
}

// ---------------- HMMA GEMMs ----------------
#define LDA 136

__global__ __launch_bounds__(256, 1) void gemm1_mma(const float* __restrict__ b1, int n) {
    extern __shared__ __half sm[];
    __half* Ah = sm;
    __half* Al = Ah + 128 * LDA;
    __half* Bh = Al + 128 * LDA;
    __half* Bl = Bh + 128 * LDA;
    int tid = threadIdx.x, wid = tid >> 5, lane = tid & 31;
    int r0 = blockIdx.x * 128;

    for (int i = tid; i < 4096; i += 256) {
        int row = i >> 5, c = i & 31;
        int gr = r0 + row;
        float4 v = (gr < n) ? ((const float4*)(g_aggx + (size_t)gr * IND))[c]
                            : make_float4(0.f, 0.f, 0.f, 0.f);
        __half h0, h1, h2, h3, l0, l1, l2, l3;
        split_h(v.x, h0, l0); split_h(v.y, h1, l1);
        split_h(v.z, h2, l2); split_h(v.w, h3, l3);
        int o = row * LDA + c * 4;
        *(__half2*)(Ah + o) = __halves2half2(h0, h1);
        *(__half2*)(Ah + o + 2) = __halves2half2(h2, h3);
        *(__half2*)(Al + o) = __halves2half2(l0, l1);
        *(__half2*)(Al + o + 2) = __halves2half2(l2, l3);
    }
    for (int i = tid; i < 2048; i += 256) {
        int row = i >> 4, seg = i & 15;
        *(uint4*)(Bh + row * LDA + seg * 8) = ((const uint4*)g_w1hi)[i];
        *(uint4*)(Bl + row * LDA + seg * 8) = ((const uint4*)g_w1lo)[i];
    }
    __syncthreads();

    uint32_t ah_b = smem_u32(Ah), al_b = smem_u32(Al);
    uint32_t bh_b = smem_u32(Bh), bl_b = smem_u32(Bl);
    int a_row = wid * 16 + (lane & 15);
    int a_co = (lane >> 4) * 8;
    uint32_t a_off = (uint32_t)(a_row * LDA + a_co) * 2;
    int b_row = (lane & 7) + ((lane >> 4) << 3);
    int b_co = ((lane >> 3) & 1) * 8;
    uint32_t b_off = (uint32_t)(b_row * LDA + b_co) * 2;

    float acc[16][4];
#pragma unroll
    for (int t = 0; t < 16; t++)
#pragma unroll
        for (int j = 0; j < 4; j++) acc[t][j] = 0.f;

#pragma unroll
    for (int ks = 0; ks < 8; ks++) {
        uint32_t ahr[4], alr[4];
        ldm_x4(ahr, ah_b + a_off + ks * 32);
        ldm_x4(alr, al_b + a_off + ks * 32);
#pragma unroll
        for (int np = 0; np < 8; np++) {
            uint32_t bhr[4], blr[4];
            uint32_t bo = b_off + (uint32_t)(np * 16 * LDA * 2) + ks * 32;
            ldm_x4(bhr, bh_b + bo);
            ldm_x4(blr, bl_b + bo);
            mma16816(acc[2 * np], ahr, bhr);
            mma16816(acc[2 * np], ahr, blr);
            mma16816(acc[2 * np], alr, bhr);
            mma16816(acc[2 * np + 1], ahr, bhr + 2);
            mma16816(acc[2 * np + 1], ahr, blr + 2);
            mma16816(acc[2 * np + 1], alr, bhr + 2);
        }
    }

    int grp = lane >> 2, qid = lane & 3;
    int rowA = r0 + wid * 16 + grp;
    int rowB = rowA + 8;
#pragma unroll
    for (int t = 0; t < 16; t++) {
        int col = t * 8 + qid * 2;
        float2 bb = *(const float2*)(b1 + col);
        if (rowA < n) {
            float2 o = make_float2(fmaxf(acc[t][0] + bb.x, 0.f),
                                   fmaxf(acc[t][1] + bb.y, 0.f));
            *(float2*)(g_h + (size_t)rowA * HID + col) = o;
        }
        if (rowB < n) {
            float2 o = make_float2(fmaxf(acc[t][2] + bb.x, 0.f),
                                   fmaxf(acc[t][3] + bb.y, 0.f));
            *(float2*)(g_h + (size_t)rowB * HID + col) = o;
        }
    }
}

// GEMM2: h216 = half((h @ W2) * dinv)  — no fp32 h2 materialization
__global__ __launch_bounds__(256, 1) void gemm2_mma(int n) {
    extern __shared__ __half sm[];
    __half* Ah = sm;
    __half* Al = Ah + 128 * LDA;
    __half* Bh = Al + 128 * LDA;
    __half* Bl = Bh + 64 * LDA;
    int tid = threadIdx.x, wid = tid >> 5, lane = tid & 31;
    int r0 = blockIdx.x * 128;

    for (int i = tid; i < 4096; i += 256) {
        int row = i >> 5, c = i & 31;
        int gr = r0 + row;
        float4 v = (gr < n) ? ((const float4*)(g_h + (size_t)gr * HID))[c]
                            : make_float4(0.f, 0.f, 0.f, 0.f);
        __half h0, h1, h2, h3, l0, l1, l2, l3;
        split_h(v.x, h0, l0); split_h(v.y, h1, l1);
        split_h(v.z, h2, l2); split_h(v.w, h3, l3);
        int o = row * LDA + c * 4;
        *(__half2*)(Ah + o) = __halves2half2(h0, h1);
        *(__half2*)(Ah + o + 2) = __halves2half2(h2, h3);
        *(__half2*)(Al + o) = __halves2half2(l0, l1);
        *(__half2*)(Al + o + 2) = __halves2half2(l2, l3);
    }
    for (int i = tid; i < 1024; i += 256) {
        int row = i >> 4, seg = i & 15;
        *(uint4*)(Bh + row * LDA + seg * 8) = ((const uint4*)g_w2hi)[i];
        *(uint4*)(Bl + row * LDA + seg * 8) = ((const uint4*)g_w2lo)[i];
    }
    __syncthreads();

    uint32_t ah_b = smem_u32(Ah), al_b = smem_u32(Al);
    uint32_t bh_b = smem_u32(Bh), bl_b = smem_u32(Bl);
    int a_row = wid * 16 + (lane & 15);
    int a_co = (lane >> 4) * 8;
    uint32_t a_off = (uint32_t)(a_row * LDA + a_co) * 2;
    int b_row = (lane & 7) + ((lane >> 4) << 3);
    int b_co = ((lane >> 3) & 1) * 8;
    uint32_t b_off = (uint32_t)(b_row * LDA + b_co) * 2;

    float acc[8][4];
#pragma unroll
    for (int t = 0; t < 8; t++)
#pragma unroll
        for (int j = 0; j < 4; j++) acc[t][j] = 0.f;

#pragma unroll
    for (int ks = 0; ks < 8; ks++) {
        uint32_t ahr[4], alr[4];
        ldm_x4(ahr, ah_b + a_off + ks * 32);
        ldm_x4(alr, al_b + a_off + ks * 32);
#pragma unroll
        for (int np = 0; np < 4; np++) {
            uint32_t bhr[4], blr[4];
            uint32_t bo = b_off + (uint32_t)(np * 16 * LDA * 2) + ks * 32;
            ldm_x4(bhr, bh_b + bo);
            ldm_x4(blr, bl_b + bo);
            mma16816(acc[2 * np], ahr, bhr);
            mma16816(acc[2 * np], ahr, blr);
            mma16816(acc[2 * np], alr, bhr);
            mma16816(acc[2 * np + 1], ahr, bhr + 2);
            mma16816(acc[2 * np + 1], ahr, blr + 2);
            mma16816(acc[2 * np + 1], alr, bhr + 2);
        }
    }

    int grp = lane >> 2, qid = lane & 3;
    int rowA = r0 + wid * 16 + grp;
    int rowB = rowA + 8;
    float dva = (rowA < n) ? g_dinv[rowA] : 0.f;
    float dvb = (rowB < n) ? g_dinv[rowB] : 0.f;
#pragma unroll
    for (int t = 0; t < 8; t++) {
        int col = t * 8 + qid * 2;
        if (rowA < n)
            *(__half2*)(g_h216 + (size_t)rowA * OUTD + col) =
                __floats2half2_rn(acc[t][0] * dva, acc[t][1] * dva);
        if (rowB < n)
            *(__half2*)(g_h216 + (size_t)rowB * OUTD + col) =
                __floats2half2_rn(acc[t][2] * dvb, acc[t][3] * dvb);
    }
}

// ---------------- launch ----------------
extern "C" void kernel_launch(void* const* d_in, const int* in_sizes, int n_in,
                              void* d_out, int out_size) {
    const float* x  = (const float*)d_in[0];
    const int*   ei = (const int*)d_in[1];
    const float* W1 = (const float*)d_in[2];
    const float* b1 = (const float*)d_in[3];
    const float* W2 = (const float*)d_in[4];
    const float* b2 = (const float*)d_in[5];
    float* out      = (float*)d_out;

    int n = in_sizes[0] / IND;
    int E = in_sizes[1] / 2;
    const int* src = ei;
    const int* dst = ei + E;

    const int SM1 = (128 * LDA * 2 + 128 * LDA * 2) * 2;
    const int SM2 = (128 * LDA * 2) * 2 + (64 * LDA * 2) * 2;
    cudaFuncSetAttribute(gemm1_mma, cudaFuncAttributeMaxDynamicSharedMemorySize, SM1);
    cudaFuncSetAttribute(gemm2_mma, cudaFuncAttributeMaxDynamicSharedMemorySize, SM2);

    const int TB = 256;
    int nb = (n + SCAN_B - 1) / SCAN_B;
    int gblk = (n + 127) / 128;
    bool vec4 = (E % 4 == 0) && ((((uintptr_t)dst) & 15) == 0) && ((((uintptr_t)src) & 15) == 0);

    w1prep_k<<<(HID * IND + TB - 1) / TB, TB>>>(W1);
    w2prep_k<<<(OUTD * IND + TB - 1) / TB, TB>>>(W2);

    void* degp = nullptr;
    cudaGetSymbolAddress(&degp, g_degc);
    cudaMemsetAsync(degp, 0, (size_t)n * sizeof(int));

    if (vec4) deg4_k<<<(E / 4 + TB - 1) / TB, TB>>>(dst, E / 4, E);
    else      deg_k<<<(E + TB - 1) / TB, TB>>>(dst, E);
    blocksum_k<<<nb, SCAN_B>>>(n);
    scanblocks_k<<<1, 128>>>(nb);
    scanfinal_k<<<nb, SCAN_B>>>(n);
    if (vec4) scatter4_k<<<(E / 4 + TB - 1) / TB, TB>>>(src, dst, E / 4, E);
    else      scatter_k<<<(E + TB - 1) / TB, TB>>>(src, dst, E);

    x16conv_k<<<(n * 16 + TB - 1) / TB, TB>>>(x, n);

    int aggBlocks = (int)(((long long)n * 32 + TB - 1) / TB);
    agg1_k<<<aggBlocks, TB>>>(n);
    gemm1_mma<<<gblk, TB, SM1>>>(b1, n);
    gemm2_mma<<<gblk, TB, SM2>>>(n);
    agg2_k<<<aggBlocks, TB>>>(b2, out, n);
}

// round 9
// speedup vs baseline: 2.1787x; 1.0210x over previous
#include <cuda_runtime.h>
#include <cuda_fp16.h>
#include <cstdint>

#define NMAX 100000
#define EMAX 1600000
#define IND 128
#define HID 128
#define OUTD 64
#define SCAN_B 1024
#define MAXBLK 128

// ---------------- scratch (static __device__, allocation-free) ----------------
__device__ int   g_degc[NMAX];
__device__ float g_dinv[NMAX];
__device__ int   g_rowptr[NMAX + 1];
__device__ int   g_pos[NMAX];
__device__ int   g_csr_src[EMAX];
__device__ unsigned long long g_scan_state[MAXBLK];  // (flag<<32)|value; 0=invalid,1=agg,2=prefix
__device__ float g_aggx[(size_t)NMAX * IND];
__device__ float g_h[(size_t)NMAX * HID];
__device__ __half g_x16[(size_t)NMAX * IND];    // x * dinv, f16 (gather table L1)
__device__ __half g_h216[(size_t)NMAX * OUTD];  // h2 * dinv, f16 (gather table L2)
// W pre-transposed to [n][k] f16 hi/lo (hi + lo == fp32 weight to ~2^-22)
__device__ __half g_w1hi[HID * IND];
__device__ __half g_w1lo[HID * IND];
__device__ __half g_w2hi[OUTD * IND];
__device__ __half g_w2lo[OUTD * IND];

__device__ __forceinline__ uint32_t smem_u32(const void* p) {
    uint32_t a;
    asm("{ .reg .u64 t; cvta.to.shared.u64 t, %1; cvt.u32.u64 %0, t; }" : "=r"(a) : "l"(p));
    return a;
}
__device__ __forceinline__ void ldm_x4(uint32_t* r, uint32_t addr) {
    asm volatile("ldmatrix.sync.aligned.m8n8.x4.shared.b16 {%0,%1,%2,%3}, [%4];"
                 : "=r"(r[0]), "=r"(r[1]), "=r"(r[2]), "=r"(r[3]) : "r"(addr));
}
__device__ __forceinline__ void mma16816(float* d, const uint32_t* a, const uint32_t* b) {
    asm volatile(
        "mma.sync.aligned.m16n8k16.row.col.f32.f16.f16.f32 "
        "{%0,%1,%2,%3}, {%4,%5,%6,%7}, {%8,%9}, {%0,%1,%2,%3};"
        : "+f"(d[0]), "+f"(d[1]), "+f"(d[2]), "+f"(d[3])
        : "r"(a[0]), "r"(a[1]), "r"(a[2]), "r"(a[3]), "r"(b[0]), "r"(b[1]));
}
__device__ __forceinline__ void split_h(float v, __half& hi, __half& lo) {
    hi = __float2half_rn(v);
    lo = __float2half_rn(v - __half2float(hi));
}
__device__ __forceinline__ unsigned long long ldvol64(const unsigned long long* p) {
    unsigned long long v;
    asm volatile("ld.volatile.global.u64 %0, [%1];" : "=l"(v) : "l"(p));
    return v;
}
__device__ __forceinline__ void stvol64(unsigned long long* p, unsigned long long v) {
    asm volatile("st.volatile.global.u64 [%0], %1;" :: "l"(p), "l"(v));
}

// ---------------- CSR build ----------------
__global__ void deg4_k(const int* __restrict__ dst, int E4, int E) {
    int i = blockIdx.x * blockDim.x + threadIdx.x;
    if (i < MAXBLK) g_scan_state[i] = 0ULL;   // reset lookback state for this replay
    if (i < E4) {
        int4 d = ((const int4*)dst)[i];
        atomicAdd(&g_degc[d.x], 1);
        atomicAdd(&g_degc[d.y], 1);
        atomicAdd(&g_degc[d.z], 1);
        atomicAdd(&g_degc[d.w], 1);
    }
    if (i == 0)
        for (int k = E4 * 4; k < E; k++) atomicAdd(&g_degc[dst[k]], 1);
}
__global__ void deg_k(const int* __restrict__ dst, int E) {
    int i = blockIdx.x * blockDim.x + threadIdx.x;
    if (i < MAXBLK) g_scan_state[i] = 0ULL;
    if (i < E) atomicAdd(&g_degc[dst[i]], 1);
}

// Single-kernel exclusive scan (decoupled lookback) + dinv. Grid must be <= 148 blocks.
__global__ __launch_bounds__(SCAN_B) void scan_k(int n) {
    __shared__ int wsum[32];
    __shared__ int sprefix;
    int b = blockIdx.x, t = threadIdx.x;
    int i = b * SCAN_B + t;
    int v = (i < n) ? g_degc[i] : 0;
    if (i < n) g_dinv[i] = rsqrtf((float)v + 1.0f);
    int lane = t & 31, w = t >> 5;
    int x = v;
#pragma unroll
    for (int o = 1; o < 32; o <<= 1) {
        int y = __shfl_up_sync(0xffffffffu, x, o);
        if (lane >= o) x += y;
    }
    if (lane == 31) wsum[w] = x;
    __syncthreads();
    if (w == 0) {
        int s = wsum[lane];
#pragma unroll
        for (int o = 1; o < 32; o <<= 1) {
            int y = __shfl_up_sync(0xffffffffu, s, o);
            if (lane >= o) s += y;
        }
        wsum[lane] = s;
    }
    __syncthreads();
    int incl = x + (w > 0 ? wsum[w - 1] : 0);
    int total = wsum[31];

    if (w == 0) {
        if (lane == 0)   // publish aggregate (block 0 publishes full prefix directly)
            stvol64(&g_scan_state[b],
                    ((unsigned long long)((b == 0) ? 2u : 1u) << 32) | (unsigned)total);
        __syncwarp();
        if (b > 0) {
            int P = 0;
            int i0 = b - 1;
            while (true) {
                int ii = i0 - lane;
                unsigned long long s = (ii >= 0) ? ldvol64(&g_scan_state[ii])
                                                 : (2ULL << 32);
                while (__any_sync(0xffffffffu, (s >> 32) == 0))
                    if ((s >> 32) == 0) s = ldvol64(&g_scan_state[ii]);
                int f = (int)(s >> 32);
                int val = (int)(unsigned)s;
                unsigned m = __ballot_sync(0xffffffffu, f == 2);
                int c;
                if (m) {
                    int L = __ffs(m) - 1;       // nearest predecessor holding full prefix
                    c = (lane <= L) ? val : 0;
                } else c = val;
#pragma unroll
                for (int o = 16; o > 0; o >>= 1) c += __shfl_down_sync(0xffffffffu, c, o);
                c = __shfl_sync(0xffffffffu, c, 0);
                P += c;
                if (m) break;
                i0 -= 32;
            }
            if (lane == 0) {
                stvol64(&g_scan_state[b], (2ULL << 32) | (unsigned)(P + total));
                sprefix = P;
            }
        } else if (lane == 0) sprefix = 0;
    }
    __syncthreads();
    int excl = incl - v + sprefix;
    if (i < n) {
        g_rowptr[i] = excl;
        g_pos[i] = excl;
        if (i == n - 1) g_rowptr[n] = excl + v;
    }
}

__global__ void scatter4_k(const int* __restrict__ src, const int* __restrict__ dst,
                           int E4, int E) {
    int i = blockIdx.x * blockDim.x + threadIdx.x;
    if (i < E4) {
        int4 s = ((const int4*)src)[i];
        int4 d = ((const int4*)dst)[i];
        g_csr_src[atomicAdd(&g_pos[d.x], 1)] = s.x;
        g_csr_src[atomicAdd(&g_pos[d.y], 1)] = s.y;
        g_csr_src[atomicAdd(&g_pos[d.z], 1)] = s.z;
        g_csr_src[atomicAdd(&g_pos[d.w], 1)] = s.w;
    }
    if (i == 0)
        for (int k = E4 * 4; k < E; k++)
            g_csr_src[atomicAdd(&g_pos[dst[k]], 1)] = src[k];
}
__global__ void scatter_k(const int* __restrict__ src, const int* __restrict__ dst, int E) {
    int e = blockIdx.x * blockDim.x + threadIdx.x;
    if (e < E) g_csr_src[atomicAdd(&g_pos[dst[e]], 1)] = src[e];
}

// ---------------- x16 = half(x * dinv) ----------------
__global__ void x16conv_k(const float* __restrict__ x, int n) {
    int i = blockIdx.x * blockDim.x + threadIdx.x;
    if (i >= n * 16) return;
    int row = i >> 4, seg = i & 15;
    float dv = g_dinv[row];
    const float4* xp = (const float4*)(x + (size_t)row * IND + seg * 8);
    float4 a = xp[0], b = xp[1];
    __half2 h0 = __floats2half2_rn(a.x * dv, a.y * dv);
    __half2 h1 = __floats2half2_rn(a.z * dv, a.w * dv);
    __half2 h2 = __floats2half2_rn(b.x * dv, b.y * dv);
    __half2 h3 = __floats2half2_rn(b.z * dv, b.w * dv);
    uint4 o;
    o.x = *(uint32_t*)&h0; o.y = *(uint32_t*)&h1;
    o.z = *(uint32_t*)&h2; o.w = *(uint32_t*)&h3;
    *(uint4*)(g_x16 + (size_t)row * IND + seg * 8) = o;
}

// ---------------- aggregation (CSR, warp per dst, fp16 gather, 8-way MLP) ----------------
__device__ __forceinline__ void acc_x16(float4& sum, uint2 p) {
    float2 a = __half22float2(*(__half2*)&p.x);
    float2 b = __half22float2(*(__half2*)&p.y);
    sum.x += a.x; sum.y += a.y; sum.z += b.x; sum.w += b.y;
}

// aggx[i] = di * (x16[i] + sum_j x16[src_j])
__global__ void agg1_k(int n) {
    int w = (blockIdx.x * blockDim.x + threadIdx.x) >> 5;
    if (w >= n) return;
    int c = threadIdx.x & 31;
    float di = g_dinv[w];
    float4 sum = make_float4(0.f, 0.f, 0.f, 0.f);
    acc_x16(sum, __ldg((const uint2*)(g_x16 + (size_t)w * IND) + c));  // self
    int j = g_rowptr[w], end = g_rowptr[w + 1];
    for (; j + 7 < end; j += 8) {
        int s0 = __ldg(&g_csr_src[j]);
        int s1 = __ldg(&g_csr_src[j + 1]);
        int s2 = __ldg(&g_csr_src[j + 2]);
        int s3 = __ldg(&g_csr_src[j + 3]);
        int s4 = __ldg(&g_csr_src[j + 4]);
        int s5 = __ldg(&g_csr_src[j + 5]);
        int s6 = __ldg(&g_csr_src[j + 6]);
        int s7 = __ldg(&g_csr_src[j + 7]);
        uint2 p0 = __ldg((const uint2*)(g_x16 + (size_t)s0 * IND) + c);
        uint2 p1 = __ldg((const uint2*)(g_x16 + (size_t)s1 * IND) + c);
        uint2 p2 = __ldg((const uint2*)(g_x16 + (size_t)s2 * IND) + c);
        uint2 p3 = __ldg((const uint2*)(g_x16 + (size_t)s3 * IND) + c);
        uint2 p4 = __ldg((const uint2*)(g_x16 + (size_t)s4 * IND) + c);
        uint2 p5 = __ldg((const uint2*)(g_x16 + (size_t)s5 * IND) + c);
        uint2 p6 = __ldg((const uint2*)(g_x16 + (size_t)s6 * IND) + c);
        uint2 p7 = __ldg((const uint2*)(g_x16 + (size_t)s7 * IND) + c);
        acc_x16(sum, p0); acc_x16(sum, p1); acc_x16(sum, p2); acc_x16(sum, p3);
        acc_x16(sum, p4); acc_x16(sum, p5); acc_x16(sum, p6); acc_x16(sum, p7);
    }
    if (j + 3 < end) {
        int s0 = __ldg(&g_csr_src[j]);
        int s1 = __ldg(&g_csr_src[j + 1]);
        int s2 = __ldg(&g_csr_src[j + 2]);
        int s3 = __ldg(&g_csr_src[j + 3]);
        uint2 p0 = __ldg((const uint2*)(g_x16 + (size_t)s0 * IND) + c);
        uint2 p1 = __ldg((const uint2*)(g_x16 + (size_t)s1 * IND) + c);
        uint2 p2 = __ldg((const uint2*)(g_x16 + (size_t)s2 * IND) + c);
        uint2 p3 = __ldg((const uint2*)(g_x16 + (size_t)s3 * IND) + c);
        acc_x16(sum, p0); acc_x16(sum, p1); acc_x16(sum, p2); acc_x16(sum, p3);
        j += 4;
    }
    for (; j < end; j++) {
        int s = __ldg(&g_csr_src[j]);
        acc_x16(sum, __ldg((const uint2*)(g_x16 + (size_t)s * IND) + c));
    }
    float4 o;
    o.x = sum.x * di; o.y = sum.y * di; o.z = sum.z * di; o.w = sum.w * di;
    ((float4*)(g_aggx + (size_t)w * IND))[c] = o;
}

// out[i] = di * (h216[i] + sum_j h216[src_j]) + b2
__global__ void agg2_k(const float* __restrict__ b2, float* __restrict__ out, int n) {
    int w = (blockIdx.x * blockDim.x + threadIdx.x) >> 5;
    if (w >= n) return;
    int c = threadIdx.x & 31;
    float di = g_dinv[w];
    float2 bb = ((const float2*)b2)[c];
    float2 sum;
    {
        uint32_t p = __ldg((const uint32_t*)(g_h216 + (size_t)w * OUTD) + c);  // self
        sum = __half22float2(*(__half2*)&p);
    }
    int j = g_rowptr[w], end = g_rowptr[w + 1];
    for (; j + 7 < end; j += 8) {
        int s0 = __ldg(&g_csr_src[j]);
        int s1 = __ldg(&g_csr_src[j + 1]);
        int s2 = __ldg(&g_csr_src[j + 2]);
        int s3 = __ldg(&g_csr_src[j + 3]);
        int s4 = __ldg(&g_csr_src[j + 4]);
        int s5 = __ldg(&g_csr_src[j + 5]);
        int s6 = __ldg(&g_csr_src[j + 6]);
        int s7 = __ldg(&g_csr_src[j + 7]);
        uint32_t p0 = __ldg((const uint32_t*)(g_h216 + (size_t)s0 * OUTD) + c);
        uint32_t p1 = __ldg((const uint32_t*)(g_h216 + (size_t)s1 * OUTD) + c);
        uint32_t p2 = __ldg((const uint32_t*)(g_h216 + (size_t)s2 * OUTD) + c);
        uint32_t p3 = __ldg((const uint32_t*)(g_h216 + (size_t)s3 * OUTD) + c);
        uint32_t p4 = __ldg((const uint32_t*)(g_h216 + (size_t)s4 * OUTD) + c);
        uint32_t p5 = __ldg((const uint32_t*)(g_h216 + (size_t)s5 * OUTD) + c);
        uint32_t p6 = __ldg((const uint32_t*)(g_h216 + (size_t)s6 * OUTD) + c);
        uint32_t p7 = __ldg((const uint32_t*)(g_h216 + (size_t)s7 * OUTD) + c);
        float2 a0 = __half22float2(*(__half2*)&p0);
        float2 a1 = __half22float2(*(__half2*)&p1);
        float2 a2 = __half22float2(*(__half2*)&p2);
        float2 a3 = __half22float2(*(__half2*)&p3);
        float2 a4 = __half22float2(*(__half2*)&p4);
        float2 a5 = __half22float2(*(__half2*)&p5);
        float2 a6 = __half22float2(*(__half2*)&p6);
        float2 a7 = __half22float2(*(__half2*)&p7);
        sum.x += ((a0.x + a1.x) + (a2.x + a3.x)) + ((a4.x + a5.x) + (a6.x + a7.x));
        sum.y += ((a0.y + a1.y) + (a2.y + a3.y)) + ((a4.y + a5.y) + (a6.y + a7.y));
    }
    if (j + 3 < end) {
        int s0 = __ldg(&g_csr_src[j]);
        int s1 = __ldg(&g_csr_src[j + 1]);
        int s2 = __ldg(&g_csr_src[j + 2]);
        int s3 = __ldg(&g_csr_src[j + 3]);
        uint32_t p0 = __ldg((const uint32_t*)(g_h216 + (size_t)s0 * OUTD) + c);
        uint32_t p1 = __ldg((const uint32_t*)(g_h216 + (size_t)s1 * OUTD) + c);
        uint32_t p2 = __ldg((const uint32_t*)(g_h216 + (size_t)s2 * OUTD) + c);
        uint32_t p3 = __ldg((const uint32_t*)(g_h216 + (size_t)s3 * OUTD) + c);
        float2 a0 = __half22float2(*(__half2*)&p0);
        float2 a1 = __half22float2(*(__half2*)&p1);
        float2 a2 = __half22float2(*(__half2*)&p2);
        float2 a3 = __half22float2(*(__half2*)&p3);
        sum.x += (a0.x + a1.x) + (a2.x + a3.x);
        sum.y += (a0.y + a1.y) + (a2.y + a3.y);
        j += 4;
    }
    for (; j < end; j++) {
        int s = __ldg(&g_csr_src[j]);
        uint32_t p = __ldg((const uint32_t*)(g_h216 + (size_t)s * OUTD) + c);
        float2 a = __half22float2(*(__half2*)&p);
        sum.x += a.x; sum.y += a.y;
    }
    float2 o;
    o.x = sum.x * di + bb.x;
    o.y = sum.y * di + bb.y;
    ((float2*)(out + (size_t)w * OUTD))[c] = o;
}

// ---------------- W prep (merged) ----------------
__global__ void wprep_k(const float* __restrict__ W1, const float* __restrict__ W2) {
    int i = blockIdx.x * blockDim.x + threadIdx.x;
    if (i < HID * IND) {
        int nn = i & 127, k = i >> 7;
        float w = W1[k * HID + nn];
        __half hi, lo; split_h(w, hi, lo);
        g_w1hi[nn * IND + k] = hi;
        g_w1lo[nn * IND + k] = lo;
    }
    int j = i - HID * IND;
    if (j >= 0 && j < OUTD * IND) {
        int nn = j & 63, k = j >> 6;
        float w = W2[k * OUTD + nn];
        __half hi, lo; split_h(w, hi, lo);
        g_w2hi[nn * IND + k] = hi;
        g_w2lo[nn * IND + k] = lo;
    }
}

// ---------------- HMMA GEMMs ----------------
#define LDA 136

__global__ __launch_bounds__(256, 1) void gemm1_mma(const float* __restrict__ b1, int n) {
    extern __shared__ __half sm[];
    __half* Ah = sm;
    __half* Al = Ah + 128 * LDA;
    __half* Bh = Al + 128 * LDA;
    __half* Bl = Bh + 128 * LDA;
    int tid = threadIdx.x, wid = tid >> 5, lane = tid & 31;
    int r0 = blockIdx.x * 128;

    for (int i = tid; i < 4096; i += 256) {
        int row = i >> 5, c = i & 31;
        int gr = r0 + row;
        float4 v = (gr < n) ? ((const float4*)(g_aggx + (size_t)gr * IND))[c]
                            : make_float4(0.f, 0.f, 0.f, 0.f);
        __half h0, h1, h2, h3, l0, l1, l2, l3;
        split_h(v.x, h0, l0); split_h(v.y, h1, l1);
        split_h(v.z, h2, l2); split_h(v.w, h3, l3);
        int o = row * LDA + c * 4;
        *(__half2*)(Ah + o) = __halves2half2(h0, h1);
        *(__half2*)(Ah + o + 2) = __halves2half2(h2, h3);
        *(__half2*)(Al + o) = __halves2half2(l0, l1);
        *(__half2*)(Al + o + 2) = __halves2half2(l2, l3);
    }
    for (int i = tid; i < 2048; i += 256) {
        int row = i >> 4, seg = i & 15;
        *(uint4*)(Bh + row * LDA + seg * 8) = ((const uint4*)g_w1hi)[i];
        *(uint4*)(Bl + row * LDA + seg * 8) = ((const uint4*)g_w1lo)[i];
    }
    __syncthreads();

    uint32_t ah_b = smem_u32(Ah), al_b = smem_u32(Al);
    uint32_t bh_b = smem_u32(Bh), bl_b = smem_u32(Bl);
    int a_row = wid * 16 + (lane & 15);
    int a_co = (lane >> 4) * 8;
    uint32_t a_off = (uint32_t)(a_row * LDA + a_co) * 2;
    int b_row = (lane & 7) + ((lane >> 4) << 3);
    int b_co = ((lane >> 3) & 1) * 8;
    uint32_t b_off = (uint32_t)(b_row * LDA + b_co) * 2;

    float acc[16][4];
#pragma unroll
    for (int t = 0; t < 16; t++)
#pragma unroll
        for (int j = 0; j < 4; j++) acc[t][j] = 0.f;

#pragma unroll
    for (int ks = 0; ks < 8; ks++) {
        uint32_t ahr[4], alr[4];
        ldm_x4(ahr, ah_b + a_off + ks * 32);
        ldm_x4(alr, al_b + a_off + ks * 32);
#pragma unroll
        for (int np = 0; np < 8; np++) {
            uint32_t bhr[4], blr[4];
            uint32_t bo = b_off + (uint32_t)(np * 16 * LDA * 2) + ks * 32;
            ldm_x4(bhr, bh_b + bo);
            ldm_x4(blr, bl_b + bo);
            mma16816(acc[2 * np], ahr, bhr);
            mma16816(acc[2 * np], ahr, blr);
            mma16816(acc[2 * np], alr, bhr);
            mma16816(acc[2 * np + 1], ahr, bhr + 2);
            mma16816(acc[2 * np + 1], ahr, blr + 2);
            mma16816(acc[2 * np + 1], alr, bhr + 2);
        }
    }

    int grp = lane >> 2, qid = lane & 3;
    int rowA = r0 + wid * 16 + grp;
    int rowB = rowA + 8;
#pragma unroll
    for (int t = 0; t < 16; t++) {
        int col = t * 8 + qid * 2;
        float2 bb = *(const float2*)(b1 + col);
        if (rowA < n) {
            float2 o = make_float2(fmaxf(acc[t][0] + bb.x, 0.f),
                                   fmaxf(acc[t][1] + bb.y, 0.f));
            *(float2*)(g_h + (size_t)rowA * HID + col) = o;
        }
        if (rowB < n) {
            float2 o = make_float2(fmaxf(acc[t][2] + bb.x, 0.f),
                                   fmaxf(acc[t][3] + bb.y, 0.f));
            *(float2*)(g_h + (size_t)rowB * HID + col) = o;
        }
    }
}

// GEMM2: h216 = half((h @ W2) * dinv)
__global__ __launch_bounds__(256, 1) void gemm2_mma(int n) {
    extern __shared__ __half sm[];
    __half* Ah = sm;
    __half* Al = Ah + 128 * LDA;
    __half* Bh = Al + 128 * LDA;
    __half* Bl = Bh + 64 * LDA;
    int tid = threadIdx.x, wid = tid >> 5, lane = tid & 31;
    int r0 = blockIdx.x * 128;

    for (int i = tid; i < 4096; i += 256) {
        int row = i >> 5, c = i & 31;
        int gr = r0 + row;
        float4 v = (gr < n) ? ((const float4*)(g_h + (size_t)gr * HID))[c]
                            : make_float4(0.f, 0.f, 0.f, 0.f);
        __half h0, h1, h2, h3, l0, l1, l2, l3;
        split_h(v.x, h0, l0); split_h(v.y, h1, l1);
        split_h(v.z, h2, l2); split_h(v.w, h3, l3);
        int o = row * LDA + c * 4;
        *(__half2*)(Ah + o) = __halves2half2(h0, h1);
        *(__half2*)(Ah + o + 2) = __halves2half2(h2, h3);
        *(__half2*)(Al + o) = __halves2half2(l0, l1);
        *(__half2*)(Al + o + 2) = __halves2half2(l2, l3);
    }
    for (int i = tid; i < 1024; i += 256) {
        int row = i >> 4, seg = i & 15;
        *(uint4*)(Bh + row * LDA + seg * 8) = ((const uint4*)g_w2hi)[i];
        *(uint4*)(Bl + row * LDA + seg * 8) = ((const uint4*)g_w2lo)[i];
    }
    __syncthreads();

    uint32_t ah_b = smem_u32(Ah), al_b = smem_u32(Al);
    uint32_t bh_b = smem_u32(Bh), bl_b = smem_u32(Bl);
    int a_row = wid * 16 + (lane & 15);
    int a_co = (lane >> 4) * 8;
    uint32_t a_off = (uint32_t)(a_row * LDA + a_co) * 2;
    int b_row = (lane & 7) + ((lane >> 4) << 3);
    int b_co = ((lane >> 3) & 1) * 8;
    uint32_t b_off = (uint32_t)(b_row * LDA + b_co) * 2;

    float acc[8][4];
#pragma unroll
    for (int t = 0; t < 8; t++)
#pragma unroll
        for (int j = 0; j < 4; j++) acc[t][j] = 0.f;

#pragma unroll
    for (int ks = 0; ks < 8; ks++) {
        uint32_t ahr[4], alr[4];
        ldm_x4(ahr, ah_b + a_off + ks * 32);
        ldm_x4(alr, al_b + a_off + ks * 32);
#pragma unroll
        for (int np = 0; np < 4; np++) {
            uint32_t bhr[4], blr[4];
            uint32_t bo = b_off + (uint32_t)(np * 16 * LDA * 2) + ks * 32;
            ldm_x4(bhr, bh_b + bo);
            ldm_x4(blr, bl_b + bo);
            mma16816(acc[2 * np], ahr, bhr);
            mma16816(acc[2 * np], ahr, blr);
            mma16816(acc[2 * np], alr, bhr);
            mma16816(acc[2 * np + 1], ahr, bhr + 2);
            mma16816(acc[2 * np + 1], ahr, blr + 2);
            mma16816(acc[2 * np + 1], alr, bhr + 2);
        }
    }

    int grp = lane >> 2, qid = lane & 3;
    int rowA = r0 + wid * 16 + grp;
    int rowB = rowA + 8;
    float dva = (rowA < n) ? g_dinv[rowA] : 0.f;
    float dvb = (rowB < n) ? g_dinv[rowB] : 0.f;
#pragma unroll
    for (int t = 0; t < 8; t++) {
        int col = t * 8 + qid * 2;
        if (rowA < n)
            *(__half2*)(g_h216 + (size_t)rowA * OUTD + col) =
                __floats2half2_rn(acc[t][0] * dva, acc[t][1] * dva);
        if (rowB < n)
            *(__half2*)(g_h216 + (size_t)rowB * OUTD + col) =
                __floats2half2_rn(acc[t][2] * dvb, acc[t][3] * dvb);
    }
}

// ---------------- launch ----------------
extern "C" void kernel_launch(void* const* d_in, const int* in_sizes, int n_in,
                              void* d_out, int out_size) {
    const float* x  = (const float*)d_in[0];
    const int*   ei = (const int*)d_in[1];
    const float* W1 = (const float*)d_in[2];
    const float* b1 = (const float*)d_in[3];
    const float* W2 = (const float*)d_in[4];
    const float* b2 = (const float*)d_in[5];
    float* out      = (float*)d_out;

    int n = in_sizes[0] / IND;
    int E = in_sizes[1] / 2;
    const int* src = ei;
    const int* dst = ei + E;

    const int SM1 = (128 * LDA * 2 + 128 * LDA * 2) * 2;
    const int SM2 = (128 * LDA * 2) * 2 + (64 * LDA * 2) * 2;
    cudaFuncSetAttribute(gemm1_mma, cudaFuncAttributeMaxDynamicSharedMemorySize, SM1);
    cudaFuncSetAttribute(gemm2_mma, cudaFuncAttributeMaxDynamicSharedMemorySize, SM2);

    const int TB = 256;
    int nb = (n + SCAN_B - 1) / SCAN_B;   // 98 <= 148: lookback co-residency holds
    int gblk = (n + 127) / 128;
    bool vec4 = (E % 4 == 0) && ((((uintptr_t)dst) & 15) == 0) && ((((uintptr_t)src) & 15) == 0);

    void* degp = nullptr;
    cudaGetSymbolAddress(&degp, g_degc);
    cudaMemsetAsync(degp, 0, (size_t)n * sizeof(int));

    if (vec4) deg4_k<<<(E / 4 + TB - 1) / TB, TB>>>(dst, E / 4, E);
    else      deg_k<<<(E + TB - 1) / TB, TB>>>(dst, E);
    scan_k<<<nb, SCAN_B>>>(n);
    if (vec4) scatter4_k<<<(E / 4 + TB - 1) / TB, TB>>>(src, dst, E / 4, E);
    else      scatter_k<<<(E + TB - 1) / TB, TB>>>(src, dst, E);
    x16conv_k<<<(n * 16 + TB - 1) / TB, TB>>>(x, n);

    int aggBlocks = (int)(((long long)n * 32 + TB - 1) / TB);
    agg1_k<<<aggBlocks, TB>>>(n);
    wprep_k<<<((HID + OUTD) * IND + TB - 1) / TB, TB>>>(W1, W2);
    gemm1_mma<<<gblk, TB, SM1>>>(b1, n);
    gemm2_mma<<<gblk, TB, SM2>>>(n);
    agg2_k<<<aggBlocks, TB>>>(b2, out, n);
}

// round 10
// speedup vs baseline: 2.6935x; 1.2363x over previous
#include <cuda_runtime.h>
#include <cuda_fp16.h>
#include <cstdint>

#define NMAX 100000
#define EMAX 1600000
#define IND 128
#define HID 128
#define OUTD 64
#define SCAN_B 1024
#define MAXBLK 128

// ---------------- scratch (static __device__, allocation-free) ----------------
__device__ int   g_degc[NMAX];
__device__ float g_dinv[NMAX];
__device__ int   g_rowptr[NMAX + 1];
__device__ int   g_pos[NMAX];
__device__ int   g_csr_src[EMAX];
__device__ unsigned long long g_scan_state[MAXBLK];  // (flag<<32)|value; 0=invalid,1=agg,2=prefix
__device__ __half g_x16[(size_t)NMAX * IND];    // x * dinv, f16 (gather table L1)
__device__ __half g_agg16[(size_t)NMAX * IND];  // layer-1 aggregate, f16 (GEMM1 A)
__device__ __half g_h16[(size_t)NMAX * HID];    // relu(agg@W1+b1), f16 (GEMM2 A)
__device__ __half g_h216[(size_t)NMAX * OUTD];  // h2 * dinv, f16 (gather table L2)
// W pre-transposed to [n][k] f16 hi/lo (hi + lo == fp32 weight to ~2^-22)
__device__ __half g_w1hi[HID * IND];
__device__ __half g_w1lo[HID * IND];
__device__ __half g_w2hi[OUTD * IND];
__device__ __half g_w2lo[OUTD * IND];

__device__ __forceinline__ uint32_t smem_u32(const void* p) {
    uint32_t a;
    asm("{ .reg .u64 t; cvta.to.shared.u64 t, %1; cvt.u32.u64 %0, t; }" : "=r"(a) : "l"(p));
    return a;
}
__device__ __forceinline__ void ldm_x4(uint32_t* r, uint32_t addr) {
    asm volatile("ldmatrix.sync.aligned.m8n8.x4.shared.b16 {%0,%1,%2,%3}, [%4];"
                 : "=r"(r[0]), "=r"(r[1]), "=r"(r[2]), "=r"(r[3]) : "r"(addr));
}
__device__ __forceinline__ void mma16816(float* d, const uint32_t* a, const uint32_t* b) {
    asm volatile(
        "mma.sync.aligned.m16n8k16.row.col.f32.f16.f16.f32 "
        "{%0,%1,%2,%3}, {%4,%5,%6,%7}, {%8,%9}, {%0,%1,%2,%3};"
        : "+f"(d[0]), "+f"(d[1]), "+f"(d[2]), "+f"(d[3])
        : "r"(a[0]), "r"(a[1]), "r"(a[2]), "r"(a[3]), "r"(b[0]), "r"(b[1]));
}
__device__ __forceinline__ void split_h(float v, __half& hi, __half& lo) {
    hi = __float2half_rn(v);
    lo = __float2half_rn(v - __half2float(hi));
}
__device__ __forceinline__ unsigned long long ldvol64(const unsigned long long* p) {
    unsigned long long v;
    asm volatile("ld.volatile.global.u64 %0, [%1];" : "=l"(v) : "l"(p));
    return v;
}
__device__ __forceinline__ void stvol64(unsigned long long* p, unsigned long long v) {
    asm volatile("st.volatile.global.u64 [%0], %1;" :: "l"(p), "l"(v));
}

// ---------------- CSR build ----------------
// NOTE: g_degc is zeroed by agg2_k at the end of each replay (and statically for call 1).
__global__ void deg4_k(const int* __restrict__ dst, int E4, int E) {
    int i = blockIdx.x * blockDim.x + threadIdx.x;
    if (i < MAXBLK) g_scan_state[i] = 0ULL;   // reset lookback state for this replay
    if (i < E4) {
        int4 d = ((const int4*)dst)[i];
        atomicAdd(&g_degc[d.x], 1);
        atomicAdd(&g_degc[d.y], 1);
        atomicAdd(&g_degc[d.z], 1);
        atomicAdd(&g_degc[d.w], 1);
    }
    if (i == 0)
        for (int k = E4 * 4; k < E; k++) atomicAdd(&g_degc[dst[k]], 1);
}
__global__ void deg_k(const int* __restrict__ dst, int E) {
    int i = blockIdx.x * blockDim.x + threadIdx.x;
    if (i < MAXBLK) g_scan_state[i] = 0ULL;
    if (i < E) atomicAdd(&g_degc[dst[i]], 1);
}

// Single-kernel exclusive scan (decoupled lookback) + dinv. Grid must be <= 148 blocks.
__global__ __launch_bounds__(SCAN_B) void scan_k(int n) {
    __shared__ int wsum[32];
    __shared__ int sprefix;
    int b = blockIdx.x, t = threadIdx.x;
    int i = b * SCAN_B + t;
    int v = (i < n) ? g_degc[i] : 0;
    if (i < n) g_dinv[i] = rsqrtf((float)v + 1.0f);
    int lane = t & 31, w = t >> 5;
    int x = v;
#pragma unroll
    for (int o = 1; o < 32; o <<= 1) {
        int y = __shfl_up_sync(0xffffffffu, x, o);
        if (lane >= o) x += y;
    }
    if (lane == 31) wsum[w] = x;
    __syncthreads();
    if (w == 0) {
        int s = wsum[lane];
#pragma unroll
        for (int o = 1; o < 32; o <<= 1) {
            int y = __shfl_up_sync(0xffffffffu, s, o);
            if (lane >= o) s += y;
        }
        wsum[lane] = s;
    }
    __syncthreads();
    int incl = x + (w > 0 ? wsum[w - 1] : 0);
    int total = wsum[31];

    if (w == 0) {
        if (lane == 0)
            stvol64(&g_scan_state[b],
                    ((unsigned long long)((b == 0) ? 2u : 1u) << 32) | (unsigned)total);
        __syncwarp();
        if (b > 0) {
            int P = 0;
            int i0 = b - 1;
            while (true) {
                int ii = i0 - lane;
                unsigned long long s = (ii >= 0) ? ldvol64(&g_scan_state[ii])
                                                 : (2ULL << 32);
                while (__any_sync(0xffffffffu, (s >> 32) == 0))
                    if ((s >> 32) == 0) s = ldvol64(&g_scan_state[ii]);
                int f = (int)(s >> 32);
                int val = (int)(unsigned)s;
                unsigned m = __ballot_sync(0xffffffffu, f == 2);
                int c;
                if (m) {
                    int L = __ffs(m) - 1;
                    c = (lane <= L) ? val : 0;
                } else c = val;
#pragma unroll
                for (int o = 16; o > 0; o >>= 1) c += __shfl_down_sync(0xffffffffu, c, o);
                c = __shfl_sync(0xffffffffu, c, 0);
                P += c;
                if (m) break;
                i0 -= 32;
            }
            if (lane == 0) {
                stvol64(&g_scan_state[b], (2ULL << 32) | (unsigned)(P + total));
                sprefix = P;
            }
        } else if (lane == 0) sprefix = 0;
    }
    __syncthreads();
    int excl = incl - v + sprefix;
    if (i < n) {
        g_rowptr[i] = excl;
        g_pos[i] = excl;
        if (i == n - 1) g_rowptr[n] = excl + v;
    }
}

__global__ void scatter4_k(const int* __restrict__ src, const int* __restrict__ dst,
                           int E4, int E) {
    int i = blockIdx.x * blockDim.x + threadIdx.x;
    if (i < E4) {
        int4 s = ((const int4*)src)[i];
        int4 d = ((const int4*)dst)[i];
        g_csr_src[atomicAdd(&g_pos[d.x], 1)] = s.x;
        g_csr_src[atomicAdd(&g_pos[d.y], 1)] = s.y;
        g_csr_src[atomicAdd(&g_pos[d.z], 1)] = s.z;
        g_csr_src[atomicAdd(&g_pos[d.w], 1)] = s.w;
    }
    if (i == 0)
        for (int k = E4 * 4; k < E; k++)
            g_csr_src[atomicAdd(&g_pos[dst[k]], 1)] = src[k];
}
__global__ void scatter_k(const int* __restrict__ src, const int* __restrict__ dst, int E) {
    int e = blockIdx.x * blockDim.x + threadIdx.x;
    if (e < E) g_csr_src[atomicAdd(&g_pos[dst[e]], 1)] = src[e];
}

// ---------------- x16 = half(x * dinv) ----------------
__global__ void x16conv_k(const float* __restrict__ x, int n) {
    int i = blockIdx.x * blockDim.x + threadIdx.x;
    if (i >= n * 16) return;
    int row = i >> 4, seg = i & 15;
    float dv = g_dinv[row];
    const float4* xp = (const float4*)(x + (size_t)row * IND + seg * 8);
    float4 a = xp[0], b = xp[1];
    __half2 h0 = __floats2half2_rn(a.x * dv, a.y * dv);
    __half2 h1 = __floats2half2_rn(a.z * dv, a.w * dv);
    __half2 h2 = __floats2half2_rn(b.x * dv, b.y * dv);
    __half2 h3 = __floats2half2_rn(b.z * dv, b.w * dv);
    uint4 o;
    o.x = *(uint32_t*)&h0; o.y = *(uint32_t*)&h1;
    o.z = *(uint32_t*)&h2; o.w = *(uint32_t*)&h3;
    *(uint4*)(g_x16 + (size_t)row * IND + seg * 8) = o;
}

// ---------------- aggregation (CSR, warp per dst, fp16 gather, 8-way MLP) ----------------
__device__ __forceinline__ void acc_x16(float4& sum, uint2 p) {
    float2 a = __half22float2(*(__half2*)&p.x);
    float2 b = __half22float2(*(__half2*)&p.y);
    sum.x += a.x; sum.y += a.y; sum.z += b.x; sum.w += b.y;
}

// agg16[i] = half(di * (x16[i] + sum_j x16[src_j]))
__global__ void agg1_k(int n) {
    int w = (blockIdx.x * blockDim.x + threadIdx.x) >> 5;
    if (w >= n) return;
    int c = threadIdx.x & 31;
    float di = g_dinv[w];
    float4 sum = make_float4(0.f, 0.f, 0.f, 0.f);
    acc_x16(sum, __ldg((const uint2*)(g_x16 + (size_t)w * IND) + c));  // self
    int j = g_rowptr[w], end = g_rowptr[w + 1];
    for (; j + 7 < end; j += 8) {
        int s0 = __ldg(&g_csr_src[j]);
        int s1 = __ldg(&g_csr_src[j + 1]);
        int s2 = __ldg(&g_csr_src[j + 2]);
        int s3 = __ldg(&g_csr_src[j + 3]);
        int s4 = __ldg(&g_csr_src[j + 4]);
        int s5 = __ldg(&g_csr_src[j + 5]);
        int s6 = __ldg(&g_csr_src[j + 6]);
        int s7 = __ldg(&g_csr_src[j + 7]);
        uint2 p0 = __ldg((const uint2*)(g_x16 + (size_t)s0 * IND) + c);
        uint2 p1 = __ldg((const uint2*)(g_x16 + (size_t)s1 * IND) + c);
        uint2 p2 = __ldg((const uint2*)(g_x16 + (size_t)s2 * IND) + c);
        uint2 p3 = __ldg((const uint2*)(g_x16 + (size_t)s3 * IND) + c);
        uint2 p4 = __ldg((const uint2*)(g_x16 + (size_t)s4 * IND) + c);
        uint2 p5 = __ldg((const uint2*)(g_x16 + (size_t)s5 * IND) + c);
        uint2 p6 = __ldg((const uint2*)(g_x16 + (size_t)s6 * IND) + c);
        uint2 p7 = __ldg((const uint2*)(g_x16 + (size_t)s7 * IND) + c);
        acc_x16(sum, p0); acc_x16(sum, p1); acc_x16(sum, p2); acc_x16(sum, p3);
        acc_x16(sum, p4); acc_x16(sum, p5); acc_x16(sum, p6); acc_x16(sum, p7);
    }
    if (j + 3 < end) {
        int s0 = __ldg(&g_csr_src[j]);
        int s1 = __ldg(&g_csr_src[j + 1]);
        int s2 = __ldg(&g_csr_src[j + 2]);
        int s3 = __ldg(&g_csr_src[j + 3]);
        uint2 p0 = __ldg((const uint2*)(g_x16 + (size_t)s0 * IND) + c);
        uint2 p1 = __ldg((const uint2*)(g_x16 + (size_t)s1 * IND) + c);
        uint2 p2 = __ldg((const uint2*)(g_x16 + (size_t)s2 * IND) + c);
        uint2 p3 = __ldg((const uint2*)(g_x16 + (size_t)s3 * IND) + c);
        acc_x16(sum, p0); acc_x16(sum, p1); acc_x16(sum, p2); acc_x16(sum, p3);
        j += 4;
    }
    for (; j < end; j++) {
        int s = __ldg(&g_csr_src[j]);
        acc_x16(sum, __ldg((const uint2*)(g_x16 + (size_t)s * IND) + c));
    }
    __half2 ha = __floats2half2_rn(sum.x * di, sum.y * di);
    __half2 hb = __floats2half2_rn(sum.z * di, sum.w * di);
    uint2 pk;
    pk.x = *(uint32_t*)&ha; pk.y = *(uint32_t*)&hb;
    *(uint2*)(g_agg16 + (size_t)w * IND + c * 4) = pk;
}

// out[i] = di * (h216[i] + sum_j h216[src_j]) + b2   (+ re-zero degc for next replay)
__global__ void agg2_k(const float* __restrict__ b2, float* __restrict__ out, int n) {
    int gi = blockIdx.x * blockDim.x + threadIdx.x;
    if (gi < n) g_degc[gi] = 0;        // restore invariant for next replay
    int w = gi >> 5;
    if (w >= n) return;
    int c = threadIdx.x & 31;
    float di = g_dinv[w];
    float2 bb = ((const float2*)b2)[c];
    float2 sum;
    {
        uint32_t p = __ldg((const uint32_t*)(g_h216 + (size_t)w * OUTD) + c);  // self
        sum = __half22float2(*(__half2*)&p);
    }
    int j = g_rowptr[w], end = g_rowptr[w + 1];
    for (; j + 7 < end; j += 8) {
        int s0 = __ldg(&g_csr_src[j]);
        int s1 = __ldg(&g_csr_src[j + 1]);
        int s2 = __ldg(&g_csr_src[j + 2]);
        int s3 = __ldg(&g_csr_src[j + 3]);
        int s4 = __ldg(&g_csr_src[j + 4]);
        int s5 = __ldg(&g_csr_src[j + 5]);
        int s6 = __ldg(&g_csr_src[j + 6]);
        int s7 = __ldg(&g_csr_src[j + 7]);
        uint32_t p0 = __ldg((const uint32_t*)(g_h216 + (size_t)s0 * OUTD) + c);
        uint32_t p1 = __ldg((const uint32_t*)(g_h216 + (size_t)s1 * OUTD) + c);
        uint32_t p2 = __ldg((const uint32_t*)(g_h216 + (size_t)s2 * OUTD) + c);
        uint32_t p3 = __ldg((const uint32_t*)(g_h216 + (size_t)s3 * OUTD) + c);
        uint32_t p4 = __ldg((const uint32_t*)(g_h216 + (size_t)s4 * OUTD) + c);
        uint32_t p5 = __ldg((const uint32_t*)(g_h216 + (size_t)s5 * OUTD) + c);
        uint32_t p6 = __ldg((const uint32_t*)(g_h216 + (size_t)s6 * OUTD) + c);
        uint32_t p7 = __ldg((const uint32_t*)(g_h216 + (size_t)s7 * OUTD) + c);
        float2 a0 = __half22float2(*(__half2*)&p0);
        float2 a1 = __half22float2(*(__half2*)&p1);
        float2 a2 = __half22float2(*(__half2*)&p2);
        float2 a3 = __half22float2(*(__half2*)&p3);
        float2 a4 = __half22float2(*(__half2*)&p4);
        float2 a5 = __half22float2(*(__half2*)&p5);
        float2 a6 = __half22float2(*(__half2*)&p6);
        float2 a7 = __half22float2(*(__half2*)&p7);
        sum.x += ((a0.x + a1.x) + (a2.x + a3.x)) + ((a4.x + a5.x) + (a6.x + a7.x));
        sum.y += ((a0.y + a1.y) + (a2.y + a3.y)) + ((a4.y + a5.y) + (a6.y + a7.y));
    }
    if (j + 3 < end) {
        int s0 = __ldg(&g_csr_src[j]);
        int s1 = __ldg(&g_csr_src[j + 1]);
        int s2 = __ldg(&g_csr_src[j + 2]);
        int s3 = __ldg(&g_csr_src[j + 3]);
        uint32_t p0 = __ldg((const uint32_t*)(g_h216 + (size_t)s0 * OUTD) + c);
        uint32_t p1 = __ldg((const uint32_t*)(g_h216 + (size_t)s1 * OUTD) + c);
        uint32_t p2 = __ldg((const uint32_t*)(g_h216 + (size_t)s2 * OUTD) + c);
        uint32_t p3 = __ldg((const uint32_t*)(g_h216 + (size_t)s3 * OUTD) + c);
        float2 a0 = __half22float2(*(__half2*)&p0);
        float2 a1 = __half22float2(*(__half2*)&p1);
        float2 a2 = __half22float2(*(__half2*)&p2);
        float2 a3 = __half22float2(*(__half2*)&p3);
        sum.x += (a0.x + a1.x) + (a2.x + a3.x);
        sum.y += (a0.y + a1.y) + (a2.y + a3.y);
        j += 4;
    }
    for (; j < end; j++) {
        int s = __ldg(&g_csr_src[j]);
        uint32_t p = __ldg((const uint32_t*)(g_h216 + (size_t)s * OUTD) + c);
        float2 a = __half22float2(*(__half2*)&p);
        sum.x += a.x; sum.y += a.y;
    }
    float2 o;
    o.x = sum.x * di + bb.x;
    o.y = sum.y * di + bb.y;
    ((float2*)(out + (size_t)w * OUTD))[c] = o;
}

// ---------------- W prep (merged) ----------------
__global__ void wprep_k(const float* __restrict__ W1, const float* __restrict__ W2) {
    int i = blockIdx.x * blockDim.x + threadIdx.x;
    if (i < HID * IND) {
        int nn = i & 127, k = i >> 7;
        float w = W1[k * HID + nn];
        __half hi, lo; split_h(w, hi, lo);
        g_w1hi[nn * IND + k] = hi;
        g_w1lo[nn * IND + k] = lo;
    }
    int j = i - HID * IND;
    if (j >= 0 && j < OUTD * IND) {
        int nn = j & 63, k = j >> 6;
        float w = W2[k * OUTD + nn];
        __half hi, lo; split_h(w, hi, lo);
        g_w2hi[nn * IND + k] = hi;
        g_w2lo[nn * IND + k] = lo;
    }
}

// ---------------- HMMA GEMMs (A f16, B hi/lo, 2 passes) ----------------
#define LDA 136

// GEMM1: h16 = half(relu(agg16 @ W1 + b1));  block = 128 rows x 128 cols, 8 warps.
__global__ __launch_bounds__(256, 1) void gemm1_mma(const float* __restrict__ b1, int n) {
    extern __shared__ __half sm[];
    __half* Ah = sm;                    // 128*136
    __half* Bh = Ah + 128 * LDA;        // 128*136 ([n][k])
    __half* Bl = Bh + 128 * LDA;
    int tid = threadIdx.x, wid = tid >> 5, lane = tid & 31;
    int r0 = blockIdx.x * 128;

    // A: straight f16 copy (linear -> padded)
    for (int i = tid; i < 2048; i += 256) {    // uint4 = 8 halves
        int row = i >> 4, seg = i & 15;
        int gr = r0 + row;
        uint4 v = (gr < n) ? ((const uint4*)(g_agg16 + (size_t)gr * IND))[seg]
                           : make_uint4(0u, 0u, 0u, 0u);
        *(uint4*)(Ah + row * LDA + seg * 8) = v;
    }
    for (int i = tid; i < 2048; i += 256) {
        int row = i >> 4, seg = i & 15;
        *(uint4*)(Bh + row * LDA + seg * 8) = ((const uint4*)g_w1hi)[i];
        *(uint4*)(Bl + row * LDA + seg * 8) = ((const uint4*)g_w1lo)[i];
    }
    __syncthreads();

    uint32_t ah_b = smem_u32(Ah);
    uint32_t bh_b = smem_u32(Bh), bl_b = smem_u32(Bl);
    int a_row = wid * 16 + (lane & 15);
    int a_co = (lane >> 4) * 8;
    uint32_t a_off = (uint32_t)(a_row * LDA + a_co) * 2;
    int b_row = (lane & 7) + ((lane >> 4) << 3);
    int b_co = ((lane >> 3) & 1) * 8;
    uint32_t b_off = (uint32_t)(b_row * LDA + b_co) * 2;

    float acc[16][4];
#pragma unroll
    for (int t = 0; t < 16; t++)
#pragma unroll
        for (int j = 0; j < 4; j++) acc[t][j] = 0.f;

#pragma unroll
    for (int ks = 0; ks < 8; ks++) {
        uint32_t ahr[4];
        ldm_x4(ahr, ah_b + a_off + ks * 32);
#pragma unroll
        for (int np = 0; np < 8; np++) {
            uint32_t bhr[4], blr[4];
            uint32_t bo = b_off + (uint32_t)(np * 16 * LDA * 2) + ks * 32;
            ldm_x4(bhr, bh_b + bo);
            ldm_x4(blr, bl_b + bo);
            mma16816(acc[2 * np], ahr, bhr);
            mma16816(acc[2 * np], ahr, blr);
            mma16816(acc[2 * np + 1], ahr, bhr + 2);
            mma16816(acc[2 * np + 1], ahr, blr + 2);
        }
    }

    int grp = lane >> 2, qid = lane & 3;
    int rowA = r0 + wid * 16 + grp;
    int rowB = rowA + 8;
#pragma unroll
    for (int t = 0; t < 16; t++) {
        int col = t * 8 + qid * 2;
        float2 bb = *(const float2*)(b1 + col);
        if (rowA < n)
            *(__half2*)(g_h16 + (size_t)rowA * HID + col) =
                __floats2half2_rn(fmaxf(acc[t][0] + bb.x, 0.f),
                                  fmaxf(acc[t][1] + bb.y, 0.f));
        if (rowB < n)
            *(__half2*)(g_h16 + (size_t)rowB * HID + col) =
                __floats2half2_rn(fmaxf(acc[t][2] + bb.x, 0.f),
                                  fmaxf(acc[t][3] + bb.y, 0.f));
    }
}

// GEMM2: h216 = half((h16 @ W2) * dinv)
__global__ __launch_bounds__(256, 1) void gemm2_mma(int n) {
    extern __shared__ __half sm[];
    __half* Ah = sm;                    // 128*136
    __half* Bh = Ah + 128 * LDA;        // 64*136
    __half* Bl = Bh + 64 * LDA;
    int tid = threadIdx.x, wid = tid >> 5, lane = tid & 31;
    int r0 = blockIdx.x * 128;

    for (int i = tid; i < 2048; i += 256) {
        int row = i >> 4, seg = i & 15;
        int gr = r0 + row;
        uint4 v = (gr < n) ? ((const uint4*)(g_h16 + (size_t)gr * HID))[seg]
                           : make_uint4(0u, 0u, 0u, 0u);
        *(uint4*)(Ah + row * LDA + seg * 8) = v;
    }
    for (int i = tid; i < 1024; i += 256) {
        int row = i >> 4, seg = i & 15;
        *(uint4*)(Bh + row * LDA + seg * 8) = ((const uint4*)g_w2hi)[i];
        *(uint4*)(Bl + row * LDA + seg * 8) = ((const uint4*)g_w2lo)[i];
    }
    __syncthreads();

    uint32_t ah_b = smem_u32(Ah);
    uint32_t bh_b = smem_u32(Bh), bl_b = smem_u32(Bl);
    int a_row = wid * 16 + (lane & 15);
    int a_co = (lane >> 4) * 8;
    uint32_t a_off = (uint32_t)(a_row * LDA + a_co) * 2;
    int b_row = (lane & 7) + ((lane >> 4) << 3);
    int b_co = ((lane >> 3) & 1) * 8;
    uint32_t b_off = (uint32_t)(b_row * LDA + b_co) * 2;

    float acc[8][4];
#pragma unroll
    for (int t = 0; t < 8; t++)
#pragma unroll
        for (int j = 0; j < 4; j++) acc[t][j] = 0.f;

#pragma unroll
    for (int ks = 0; ks < 8; ks++) {
        uint32_t ahr[4];
        ldm_x4(ahr, ah_b + a_off + ks * 32);
#pragma unroll
        for (int np = 0; np < 4; np++) {
            uint32_t bhr[4], blr[4];
            uint32_t bo = b_off + (uint32_t)(np * 16 * LDA * 2) + ks * 32;
            ldm_x4(bhr, bh_b + bo);
            ldm_x4(blr, bl_b + bo);
            mma16816(acc[2 * np], ahr, bhr);
            mma16816(acc[2 * np], ahr, blr);
            mma16816(acc[2 * np + 1], ahr, bhr + 2);
            mma16816(acc[2 * np + 1], ahr, blr + 2);
        }
    }

    int grp = lane >> 2, qid = lane & 3;
    int rowA = r0 + wid * 16 + grp;
    int rowB = rowA + 8;
    float dva = (rowA < n) ? g_dinv[rowA] : 0.f;
    float dvb = (rowB < n) ? g_dinv[rowB] : 0.f;
#pragma unroll
    for (int t = 0; t < 8; t++) {
        int col = t * 8 + qid * 2;
        if (rowA < n)
            *(__half2*)(g_h216 + (size_t)rowA * OUTD + col) =
                __floats2half2_rn(acc[t][0] * dva, acc[t][1] * dva);
        if (rowB < n)
            *(__half2*)(g_h216 + (size_t)rowB * OUTD + col) =
                __floats2half2_rn(acc[t][2] * dvb, acc[t][3] * dvb);
    }
}

// ---------------- launch ----------------
extern "C" void kernel_launch(void* const* d_in, const int* in_sizes, int n_in,
                              void* d_out, int out_size) {
    const float* x  = (const float*)d_in[0];
    const int*   ei = (const int*)d_in[1];
    const float* W1 = (const float*)d_in[2];
    const float* b1 = (const float*)d_in[3];
    const float* W2 = (const float*)d_in[4];
    const float* b2 = (const float*)d_in[5];
    float* out      = (float*)d_out;

    int n = in_sizes[0] / IND;
    int E = in_sizes[1] / 2;
    const int* src = ei;
    const int* dst = ei + E;

    const int SM1 = 3 * (128 * LDA * 2);               // 104448
    const int SM2 = (128 * LDA * 2) + 2 * (64 * LDA * 2);  // 69632
    cudaFuncSetAttribute(gemm1_mma, cudaFuncAttributeMaxDynamicSharedMemorySize, SM1);
    cudaFuncSetAttribute(gemm2_mma, cudaFuncAttributeMaxDynamicSharedMemorySize, SM2);

    const int TB = 256;
    int nb = (n + SCAN_B - 1) / SCAN_B;   // 98 <= 148: lookback co-residency holds
    int gblk = (n + 127) / 128;
    bool vec4 = (E % 4 == 0) && ((((uintptr_t)dst) & 15) == 0) && ((((uintptr_t)src) & 15) == 0);

    if (vec4) deg4_k<<<(E / 4 + TB - 1) / TB, TB>>>(dst, E / 4, E);
    else      deg_k<<<(E + TB - 1) / TB, TB>>>(dst, E);
    scan_k<<<nb, SCAN_B>>>(n);
    if (vec4) scatter4_k<<<(E / 4 + TB - 1) / TB, TB>>>(src, dst, E / 4, E);
    else      scatter_k<<<(E + TB - 1) / TB, TB>>>(src, dst, E);
    x16conv_k<<<(n * 16 + TB - 1) / TB, TB>>>(x, n);

    int aggBlocks = (int)(((long long)n * 32 + TB - 1) / TB);
    agg1_k<<<aggBlocks, TB>>>(n);
    wprep_k<<<((HID + OUTD) * IND + TB - 1) / TB, TB>>>(W1, W2);
    gemm1_mma<<<gblk, TB, SM1>>>(b1, n);
    gemm2_mma<<<gblk, TB, SM2>>>(n);
    agg2_k<<<aggBlocks, TB>>>(b2, out, n);
}

// round 11
// speedup vs baseline: 2.8064x; 1.0419x over previous
#include <cuda_runtime.h>
#include <cuda_fp16.h>
#include <cstdint>

#define NMAX 100000
#define EMAX 1600000
#define IND 128
#define HID 128
#define OUTD 64
#define SCAN_B 1024
#define MAXBLK 128

// ---------------- scratch (static __device__, allocation-free) ----------------
__device__ int   g_degc[NMAX];
__device__ float g_dinv[NMAX];
__device__ int   g_rowptr[NMAX + 1];
__device__ int   g_pos[NMAX];
__device__ int   g_csr_src[EMAX];
__device__ unsigned long long g_scan_state[MAXBLK];  // (flag<<32)|value; 0=invalid,1=agg,2=prefix
__device__ __half g_x16[(size_t)NMAX * IND];    // x * dinv, f16 (gather table L1)
__device__ __half g_agg16[(size_t)NMAX * IND];  // layer-1 aggregate, f16 (GEMM A)
__device__ __half g_h216[(size_t)NMAX * OUTD];  // h2 * dinv, f16 (gather table L2)
// W pre-transposed to [n][k] f16 hi/lo (hi + lo == fp32 weight to ~2^-22)
__device__ __half g_w1hi[HID * IND];
__device__ __half g_w1lo[HID * IND];
__device__ __half g_w2hi[OUTD * IND];
__device__ __half g_w2lo[OUTD * IND];

__device__ __forceinline__ uint32_t smem_u32(const void* p) {
    uint32_t a;
    asm("{ .reg .u64 t; cvta.to.shared.u64 t, %1; cvt.u32.u64 %0, t; }" : "=r"(a) : "l"(p));
    return a;
}
__device__ __forceinline__ void ldm_x4(uint32_t* r, uint32_t addr) {
    asm volatile("ldmatrix.sync.aligned.m8n8.x4.shared.b16 {%0,%1,%2,%3}, [%4];"
                 : "=r"(r[0]), "=r"(r[1]), "=r"(r[2]), "=r"(r[3]) : "r"(addr));
}
__device__ __forceinline__ void mma16816(float* d, const uint32_t* a, const uint32_t* b) {
    asm volatile(
        "mma.sync.aligned.m16n8k16.row.col.f32.f16.f16.f32 "
        "{%0,%1,%2,%3}, {%4,%5,%6,%7}, {%8,%9}, {%0,%1,%2,%3};"
        : "+f"(d[0]), "+f"(d[1]), "+f"(d[2]), "+f"(d[3])
        : "r"(a[0]), "r"(a[1]), "r"(a[2]), "r"(a[3]), "r"(b[0]), "r"(b[1]));
}
__device__ __forceinline__ void split_h(float v, __half& hi, __half& lo) {
    hi = __float2half_rn(v);
    lo = __float2half_rn(v - __half2float(hi));
}
__device__ __forceinline__ unsigned long long ldvol64(const unsigned long long* p) {
    unsigned long long v;
    asm volatile("ld.volatile.global.u64 %0, [%1];" : "=l"(v) : "l"(p));
    return v;
}
__device__ __forceinline__ void stvol64(unsigned long long* p, unsigned long long v) {
    asm volatile("st.volatile.global.u64 [%0], %1;" :: "l"(p), "l"(v));
}

// ---------------- CSR build ----------------
// NOTE: g_degc is zeroed by agg2_k at the end of each replay (and statically for call 1).
__global__ void deg4_k(const int* __restrict__ dst, int E4, int E) {
    int i = blockIdx.x * blockDim.x + threadIdx.x;
    if (i < MAXBLK) g_scan_state[i] = 0ULL;   // reset lookback state for this replay
    if (i < E4) {
        int4 d = ((const int4*)dst)[i];
        atomicAdd(&g_degc[d.x], 1);
        atomicAdd(&g_degc[d.y], 1);
        atomicAdd(&g_degc[d.z], 1);
        atomicAdd(&g_degc[d.w], 1);
    }
    if (i == 0)
        for (int k = E4 * 4; k < E; k++) atomicAdd(&g_degc[dst[k]], 1);
}
__global__ void deg_k(const int* __restrict__ dst, int E) {
    int i = blockIdx.x * blockDim.x + threadIdx.x;
    if (i < MAXBLK) g_scan_state[i] = 0ULL;
    if (i < E) atomicAdd(&g_degc[dst[i]], 1);
}

// Single-kernel exclusive scan (decoupled lookback) + dinv + x16 conversion.
// Grid must be <= 148 blocks (co-residency). Block b owns rows [b*1024, b*1024+1024).
__global__ __launch_bounds__(SCAN_B) void scanx_k(const float* __restrict__ x, int n) {
    __shared__ int wsum[32];
    __shared__ int sprefix;
    int b = blockIdx.x, t = threadIdx.x;
    int i = b * SCAN_B + t;
    int v = (i < n) ? g_degc[i] : 0;
    if (i < n) g_dinv[i] = rsqrtf((float)v + 1.0f);
    int lane = t & 31, w = t >> 5;
    int x_ = v;
#pragma unroll
    for (int o = 1; o < 32; o <<= 1) {
        int y = __shfl_up_sync(0xffffffffu, x_, o);
        if (lane >= o) x_ += y;
    }
    if (lane == 31) wsum[w] = x_;
    __syncthreads();
    if (w == 0) {
        int s = wsum[lane];
#pragma unroll
        for (int o = 1; o < 32; o <<= 1) {
            int y = __shfl_up_sync(0xffffffffu, s, o);
            if (lane >= o) s += y;
        }
        wsum[lane] = s;
    }
    __syncthreads();
    int incl = x_ + (w > 0 ? wsum[w - 1] : 0);
    int total = wsum[31];

    if (w == 0) {
        if (lane == 0)
            stvol64(&g_scan_state[b],
                    ((unsigned long long)((b == 0) ? 2u : 1u) << 32) | (unsigned)total);
        __syncwarp();
        if (b > 0) {
            int P = 0;
            int i0 = b - 1;
            while (true) {
                int ii = i0 - lane;
                unsigned long long s = (ii >= 0) ? ldvol64(&g_scan_state[ii])
                                                 : (2ULL << 32);
                while (__any_sync(0xffffffffu, (s >> 32) == 0))
                    if ((s >> 32) == 0) s = ldvol64(&g_scan_state[ii]);
                int f = (int)(s >> 32);
                int val = (int)(unsigned)s;
                unsigned m = __ballot_sync(0xffffffffu, f == 2);
                int c;
                if (m) {
                    int L = __ffs(m) - 1;
                    c = (lane <= L) ? val : 0;
                } else c = val;
#pragma unroll
                for (int o = 16; o > 0; o >>= 1) c += __shfl_down_sync(0xffffffffu, c, o);
                c = __shfl_sync(0xffffffffu, c, 0);
                P += c;
                if (m) break;
                i0 -= 32;
            }
            if (lane == 0) {
                stvol64(&g_scan_state[b], (2ULL << 32) | (unsigned)(P + total));
                sprefix = P;
            }
        } else if (lane == 0) sprefix = 0;
    }
    __syncthreads();
    int excl = incl - v + sprefix;
    if (i < n) {
        g_rowptr[i] = excl;
        g_pos[i] = excl;
        if (i == n - 1) g_rowptr[n] = excl + v;
    }
    // x16 conversion for this block's rows (dinv visible: written above + syncthreads)
    int base = b * SCAN_B;
    for (int idx = t; idx < SCAN_B * 16; idx += SCAN_B) {
        int row = base + (idx >> 4);
        if (row >= n) break;
        int seg = idx & 15;
        float dv = g_dinv[row];
        const float4* xp = (const float4*)(x + (size_t)row * IND + seg * 8);
        float4 a = xp[0], bb = xp[1];
        __half2 h0 = __floats2half2_rn(a.x * dv, a.y * dv);
        __half2 h1 = __floats2half2_rn(a.z * dv, a.w * dv);
        __half2 h2 = __floats2half2_rn(bb.x * dv, bb.y * dv);
        __half2 h3 = __floats2half2_rn(bb.z * dv, bb.w * dv);
        uint4 o;
        o.x = *(uint32_t*)&h0; o.y = *(uint32_t*)&h1;
        o.z = *(uint32_t*)&h2; o.w = *(uint32_t*)&h3;
        *(uint4*)(g_x16 + (size_t)row * IND + seg * 8) = o;
    }
}

__global__ void scatter4_k(const int* __restrict__ src, const int* __restrict__ dst,
                           int E4, int E) {
    int i = blockIdx.x * blockDim.x + threadIdx.x;
    if (i < E4) {
        int4 s = ((const int4*)src)[i];
        int4 d = ((const int4*)dst)[i];
        g_csr_src[atomicAdd(&g_pos[d.x], 1)] = s.x;
        g_csr_src[atomicAdd(&g_pos[d.y], 1)] = s.y;
        g_csr_src[atomicAdd(&g_pos[d.z], 1)] = s.z;
        g_csr_src[atomicAdd(&g_pos[d.w], 1)] = s.w;
    }
    if (i == 0)
        for (int k = E4 * 4; k < E; k++)
            g_csr_src[atomicAdd(&g_pos[dst[k]], 1)] = src[k];
}
__global__ void scatter_k(const int* __restrict__ src, const int* __restrict__ dst, int E) {
    int e = blockIdx.x * blockDim.x + threadIdx.x;
    if (e < E) g_csr_src[atomicAdd(&g_pos[dst[e]], 1)] = src[e];
}

// ---------------- aggregation (CSR, warp per dst, fp16 gather, 8-way MLP) ----------------
__device__ __forceinline__ void acc_x16(float4& sum, uint2 p) {
    float2 a = __half22float2(*(__half2*)&p.x);
    float2 b = __half22float2(*(__half2*)&p.y);
    sum.x += a.x; sum.y += a.y; sum.z += b.x; sum.w += b.y;
}

// agg16[i] = half(di * (x16[i] + sum_j x16[src_j]))
__global__ void agg1_k(int n) {
    int w = (blockIdx.x * blockDim.x + threadIdx.x) >> 5;
    if (w >= n) return;
    int c = threadIdx.x & 31;
    float di = g_dinv[w];
    float4 sum = make_float4(0.f, 0.f, 0.f, 0.f);
    acc_x16(sum, __ldg((const uint2*)(g_x16 + (size_t)w * IND) + c));  // self
    int j = g_rowptr[w], end = g_rowptr[w + 1];
    for (; j + 7 < end; j += 8) {
        int s0 = __ldg(&g_csr_src[j]);
        int s1 = __ldg(&g_csr_src[j + 1]);
        int s2 = __ldg(&g_csr_src[j + 2]);
        int s3 = __ldg(&g_csr_src[j + 3]);
        int s4 = __ldg(&g_csr_src[j + 4]);
        int s5 = __ldg(&g_csr_src[j + 5]);
        int s6 = __ldg(&g_csr_src[j + 6]);
        int s7 = __ldg(&g_csr_src[j + 7]);
        uint2 p0 = __ldg((const uint2*)(g_x16 + (size_t)s0 * IND) + c);
        uint2 p1 = __ldg((const uint2*)(g_x16 + (size_t)s1 * IND) + c);
        uint2 p2 = __ldg((const uint2*)(g_x16 + (size_t)s2 * IND) + c);
        uint2 p3 = __ldg((const uint2*)(g_x16 + (size_t)s3 * IND) + c);
        uint2 p4 = __ldg((const uint2*)(g_x16 + (size_t)s4 * IND) + c);
        uint2 p5 = __ldg((const uint2*)(g_x16 + (size_t)s5 * IND) + c);
        uint2 p6 = __ldg((const uint2*)(g_x16 + (size_t)s6 * IND) + c);
        uint2 p7 = __ldg((const uint2*)(g_x16 + (size_t)s7 * IND) + c);
        acc_x16(sum, p0); acc_x16(sum, p1); acc_x16(sum, p2); acc_x16(sum, p3);
        acc_x16(sum, p4); acc_x16(sum, p5); acc_x16(sum, p6); acc_x16(sum, p7);
    }
    if (j + 3 < end) {
        int s0 = __ldg(&g_csr_src[j]);
        int s1 = __ldg(&g_csr_src[j + 1]);
        int s2 = __ldg(&g_csr_src[j + 2]);
        int s3 = __ldg(&g_csr_src[j + 3]);
        uint2 p0 = __ldg((const uint2*)(g_x16 + (size_t)s0 * IND) + c);
        uint2 p1 = __ldg((const uint2*)(g_x16 + (size_t)s1 * IND) + c);
        uint2 p2 = __ldg((const uint2*)(g_x16 + (size_t)s2 * IND) + c);
        uint2 p3 = __ldg((const uint2*)(g_x16 + (size_t)s3 * IND) + c);
        acc_x16(sum, p0); acc_x16(sum, p1); acc_x16(sum, p2); acc_x16(sum, p3);
        j += 4;
    }
    for (; j < end; j++) {
        int s = __ldg(&g_csr_src[j]);
        acc_x16(sum, __ldg((const uint2*)(g_x16 + (size_t)s * IND) + c));
    }
    __half2 ha = __floats2half2_rn(sum.x * di, sum.y * di);
    __half2 hb = __floats2half2_rn(sum.z * di, sum.w * di);
    uint2 pk;
    pk.x = *(uint32_t*)&ha; pk.y = *(uint32_t*)&hb;
    *(uint2*)(g_agg16 + (size_t)w * IND + c * 4) = pk;
}

// out[i] = di * (h216[i] + sum_j h216[src_j]) + b2   (+ re-zero degc for next replay)
__global__ void agg2_k(const float* __restrict__ b2, float* __restrict__ out, int n) {
    int gi = blockIdx.x * blockDim.x + threadIdx.x;
    if (gi < n) g_degc[gi] = 0;        // restore invariant for next replay
    int w = gi >> 5;
    if (w >= n) return;
    int c = threadIdx.x & 31;
    float di = g_dinv[w];
    float2 bb = ((const float2*)b2)[c];
    float2 sum;
    {
        uint32_t p = __ldg((const uint32_t*)(g_h216 + (size_t)w * OUTD) + c);  // self
        sum = __half22float2(*(__half2*)&p);
    }
    int j = g_rowptr[w], end = g_rowptr[w + 1];
    for (; j + 7 < end; j += 8) {
        int s0 = __ldg(&g_csr_src[j]);
        int s1 = __ldg(&g_csr_src[j + 1]);
        int s2 = __ldg(&g_csr_src[j + 2]);
        int s3 = __ldg(&g_csr_src[j + 3]);
        int s4 = __ldg(&g_csr_src[j + 4]);
        int s5 = __ldg(&g_csr_src[j + 5]);
        int s6 = __ldg(&g_csr_src[j + 6]);
        int s7 = __ldg(&g_csr_src[j + 7]);
        uint32_t p0 = __ldg((const uint32_t*)(g_h216 + (size_t)s0 * OUTD) + c);
        uint32_t p1 = __ldg((const uint32_t*)(g_h216 + (size_t)s1 * OUTD) + c);
        uint32_t p2 = __ldg((const uint32_t*)(g_h216 + (size_t)s2 * OUTD) + c);
        uint32_t p3 = __ldg((const uint32_t*)(g_h216 + (size_t)s3 * OUTD) + c);
        uint32_t p4 = __ldg((const uint32_t*)(g_h216 + (size_t)s4 * OUTD) + c);
        uint32_t p5 = __ldg((const uint32_t*)(g_h216 + (size_t)s5 * OUTD) + c);
        uint32_t p6 = __ldg((const uint32_t*)(g_h216 + (size_t)s6 * OUTD) + c);
        uint32_t p7 = __ldg((const uint32_t*)(g_h216 + (size_t)s7 * OUTD) + c);
        float2 a0 = __half22float2(*(__half2*)&p0);
        float2 a1 = __half22float2(*(__half2*)&p1);
        float2 a2 = __half22float2(*(__half2*)&p2);
        float2 a3 = __half22float2(*(__half2*)&p3);
        float2 a4 = __half22float2(*(__half2*)&p4);
        float2 a5 = __half22float2(*(__half2*)&p5);
        float2 a6 = __half22float2(*(__half2*)&p6);
        float2 a7 = __half22float2(*(__half2*)&p7);
        sum.x += ((a0.x + a1.x) + (a2.x + a3.x)) + ((a4.x + a5.x) + (a6.x + a7.x));
        sum.y += ((a0.y + a1.y) + (a2.y + a3.y)) + ((a4.y + a5.y) + (a6.y + a7.y));
    }
    if (j + 3 < end) {
        int s0 = __ldg(&g_csr_src[j]);
        int s1 = __ldg(&g_csr_src[j + 1]);
        int s2 = __ldg(&g_csr_src[j + 2]);
        int s3 = __ldg(&g_csr_src[j + 3]);
        uint32_t p0 = __ldg((const uint32_t*)(g_h216 + (size_t)s0 * OUTD) + c);
        uint32_t p1 = __ldg((const uint32_t*)(g_h216 + (size_t)s1 * OUTD) + c);
        uint32_t p2 = __ldg((const uint32_t*)(g_h216 + (size_t)s2 * OUTD) + c);
        uint32_t p3 = __ldg((const uint32_t*)(g_h216 + (size_t)s3 * OUTD) + c);
        float2 a0 = __half22float2(*(__half2*)&p0);
        float2 a1 = __half22float2(*(__half2*)&p1);
        float2 a2 = __half22float2(*(__half2*)&p2);
        float2 a3 = __half22float2(*(__half2*)&p3);
        sum.x += (a0.x + a1.x) + (a2.x + a3.x);
        sum.y += (a0.y + a1.y) + (a2.y + a3.y);
        j += 4;
    }
    for (; j < end; j++) {
        int s = __ldg(&g_csr_src[j]);
        uint32_t p = __ldg((const uint32_t*)(g_h216 + (size_t)s * OUTD) + c);
        float2 a = __half22float2(*(__half2*)&p);
        sum.x += a.x; sum.y += a.y;
    }
    float2 o;
    o.x = sum.x * di + bb.x;
    o.y = sum.y * di + bb.y;
    ((float2*)(out + (size_t)w * OUTD))[c] = o;
}

// ---------------- W prep (merged) ----------------
__global__ void wprep_k(const float* __restrict__ W1, const float* __restrict__ W2) {
    int i = blockIdx.x * blockDim.x + threadIdx.x;
    if (i < HID * IND) {
        int nn = i & 127, k = i >> 7;
        float w = W1[k * HID + nn];
        __half hi, lo; split_h(w, hi, lo);
        g_w1hi[nn * IND + k] = hi;
        g_w1lo[nn * IND + k] = lo;
    }
    int j = i - HID * IND;
    if (j >= 0 && j < OUTD * IND) {
        int nn = j & 63, k = j >> 6;
        float w = W2[k * OUTD + nn];
        __half hi, lo; split_h(w, hi, lo);
        g_w2hi[nn * IND + k] = hi;
        g_w2lo[nn * IND + k] = lo;
    }
}

// ---------------- fused HMMA GEMM1+GEMM2 ----------------
// Pass 1: h16 = relu(agg16 @ W1 + b1)  -> written back into A smem (per-warp-private rows)
// Pass 2: h216 = half((h16 @ W2) * dinv) -> global
#define LDA 136

__global__ __launch_bounds__(256, 1) void gemmf_mma(const float* __restrict__ b1, int n) {
    extern __shared__ __half sm[];
    __half* Ah  = sm;                     // 128*136 (A, then h16)
    __half* B1h = Ah + 128 * LDA;         // 128*136
    __half* B1l = B1h + 128 * LDA;
    __half* B2h = B1l + 128 * LDA;        // 64*136
    __half* B2l = B2h + 64 * LDA;
    int tid = threadIdx.x, wid = tid >> 5, lane = tid & 31;
    int r0 = blockIdx.x * 128;

    for (int i = tid; i < 2048; i += 256) {    // A: f16 copy (linear -> padded)
        int row = i >> 4, seg = i & 15;
        int gr = r0 + row;
        uint4 v = (gr < n) ? ((const uint4*)(g_agg16 + (size_t)gr * IND))[seg]
                           : make_uint4(0u, 0u, 0u, 0u);
        *(uint4*)(Ah + row * LDA + seg * 8) = v;
    }
    for (int i = tid; i < 2048; i += 256) {
        int row = i >> 4, seg = i & 15;
        *(uint4*)(B1h + row * LDA + seg * 8) = ((const uint4*)g_w1hi)[i];
        *(uint4*)(B1l + row * LDA + seg * 8) = ((const uint4*)g_w1lo)[i];
    }
    for (int i = tid; i < 1024; i += 256) {
        int row = i >> 4, seg = i & 15;
        *(uint4*)(B2h + row * LDA + seg * 8) = ((const uint4*)g_w2hi)[i];
        *(uint4*)(B2l + row * LDA + seg * 8) = ((const uint4*)g_w2lo)[i];
    }
    __syncthreads();

    uint32_t ah_b = smem_u32(Ah);
    uint32_t b1h_b = smem_u32(B1h), b1l_b = smem_u32(B1l);
    uint32_t b2h_b = smem_u32(B2h), b2l_b = smem_u32(B2l);
    int a_row = wid * 16 + (lane & 15);
    int a_co = (lane >> 4) * 8;
    uint32_t a_off = (uint32_t)(a_row * LDA + a_co) * 2;
    int b_row = (lane & 7) + ((lane >> 4) << 3);
    int b_co = ((lane >> 3) & 1) * 8;
    uint32_t b_off = (uint32_t)(b_row * LDA + b_co) * 2;

    int grp = lane >> 2, qid = lane & 3;
    int rowAl = wid * 16 + grp;       // local row in tile
    int rowBl = rowAl + 8;

    // ---- pass 1: acc1 = A @ W1 ----
    {
        float acc[16][4];
#pragma unroll
        for (int t = 0; t < 16; t++)
#pragma unroll
            for (int j = 0; j < 4; j++) acc[t][j] = 0.f;

#pragma unroll
        for (int ks = 0; ks < 8; ks++) {
            uint32_t ahr[4];
            ldm_x4(ahr, ah_b + a_off + ks * 32);
#pragma unroll
            for (int np = 0; np < 8; np++) {
                uint32_t bhr[4], blr[4];
                uint32_t bo = b_off + (uint32_t)(np * 16 * LDA * 2) + ks * 32;
                ldm_x4(bhr, b1h_b + bo);
                ldm_x4(blr, b1l_b + bo);
                mma16816(acc[2 * np], ahr, bhr);
                mma16816(acc[2 * np], ahr, blr);
                mma16816(acc[2 * np + 1], ahr, bhr + 2);
                mma16816(acc[2 * np + 1], ahr, blr + 2);
            }
        }
        // epilogue 1: bias + relu -> h16 into A smem (own-warp rows only)
#pragma unroll
        for (int t = 0; t < 16; t++) {
            int col = t * 8 + qid * 2;
            float2 bb = *(const float2*)(b1 + col);
            *(__half2*)(Ah + rowAl * LDA + col) =
                __floats2half2_rn(fmaxf(acc[t][0] + bb.x, 0.f),
                                  fmaxf(acc[t][1] + bb.y, 0.f));
            *(__half2*)(Ah + rowBl * LDA + col) =
                __floats2half2_rn(fmaxf(acc[t][2] + bb.x, 0.f),
                                  fmaxf(acc[t][3] + bb.y, 0.f));
        }
    }
    __syncwarp();

    // ---- pass 2: acc2 = h16 @ W2 ----
    {
        float acc[8][4];
#pragma unroll
        for (int t = 0; t < 8; t++)
#pragma unroll
            for (int j = 0; j < 4; j++) acc[t][j] = 0.f;

#pragma unroll
        for (int ks = 0; ks < 8; ks++) {
            uint32_t ahr[4];
            ldm_x4(ahr, ah_b + a_off + ks * 32);
#pragma unroll
            for (int np = 0; np < 4; np++) {
                uint32_t bhr[4], blr[4];
                uint32_t bo = b_off + (uint32_t)(np * 16 * LDA * 2) + ks * 32;
                ldm_x4(bhr, b2h_b + bo);
                ldm_x4(blr, b2l_b + bo);
                mma16816(acc[2 * np], ahr, bhr);
                mma16816(acc[2 * np], ahr, blr);
                mma16816(acc[2 * np + 1], ahr, bhr + 2);
                mma16816(acc[2 * np + 1], ahr, blr + 2);
            }
        }
        int rowA = r0 + rowAl;
        int rowB = r0 + rowBl;
        float dva = (rowA < n) ? g_dinv[rowA] : 0.f;
        float dvb = (rowB < n) ? g_dinv[rowB] : 0.f;
#pragma unroll
        for (int t = 0; t < 8; t++) {
            int col = t * 8 + qid * 2;
            if (rowA < n)
                *(__half2*)(g_h216 + (size_t)rowA * OUTD + col) =
                    __floats2half2_rn(acc[t][0] * dva, acc[t][1] * dva);
            if (rowB < n)
                *(__half2*)(g_h216 + (size_t)rowB * OUTD + col) =
                    __floats2half2_rn(acc[t][2] * dvb, acc[t][3] * dvb);
        }
    }
}

// ---------------- launch ----------------
extern "C" void kernel_launch(void* const* d_in, const int* in_sizes, int n_in,
                              void* d_out, int out_size) {
    const float* x  = (const float*)d_in[0];
    const int*   ei = (const int*)d_in[1];
    const float* W1 = (const float*)d_in[2];
    const float* b1 = (const float*)d_in[3];
    const float* W2 = (const float*)d_in[4];
    const float* b2 = (const float*)d_in[5];
    float* out      = (float*)d_out;

    int n = in_sizes[0] / IND;
    int E = in_sizes[1] / 2;
    const int* src = ei;
    const int* dst = ei + E;

    const int SMF = 3 * (128 * LDA * 2) + 2 * (64 * LDA * 2);  // 139264
    cudaFuncSetAttribute(gemmf_mma, cudaFuncAttributeMaxDynamicSharedMemorySize, SMF);

    const int TB = 256;
    int nb = (n + SCAN_B - 1) / SCAN_B;   // 98 <= 148: lookback co-residency holds
    int gblk = (n + 127) / 128;
    bool vec4 = (E % 4 == 0) && ((((uintptr_t)dst) & 15) == 0) && ((((uintptr_t)src) & 15) == 0);

    if (vec4) deg4_k<<<(E / 4 + TB - 1) / TB, TB>>>(dst, E / 4, E);
    else      deg_k<<<(E + TB - 1) / TB, TB>>>(dst, E);
    scanx_k<<<nb, SCAN_B>>>(x, n);
    if (vec4) scatter4_k<<<(E / 4 + TB - 1) / TB, TB>>>(src, dst, E / 4, E);
    else      scatter_k<<<(E + TB - 1) / TB, TB>>>(src, dst, E);

    int aggBlocks = (int)(((long long)n * 32 + TB - 1) / TB);
    agg1_k<<<aggBlocks, TB>>>(n);
    wprep_k<<<((HID + OUTD) * IND + TB - 1) / TB, TB>>>(W1, W2);
    gemmf_mma<<<gblk, TB, SMF>>>(b1, n);
    agg2_k<<<aggBlocks, TB>>>(b2, out, n);
}